// round 8
// baseline (speedup 1.0000x reference)
#include <cuda_runtime.h>
#include <cuda_bf16.h>
#include <math.h>
#include <stdint.h>

// Problem constants
#define BT   2048
#define TT   1024
#define DD   768
#define HH   12
#define HS   64
#define NKV  3
#define NL   12
#define II   2048
#define VV   50257
#define KVD  192
#define QKV  1152     // 768 q + 192 k + 192 v
#define GU   4096     // 2048 gate + 2048 up
#define EPS_ 1e-6f

// ---------------- fp32 scratch ----------------
__device__ float g_x[BT * DD];
__device__ float g_qkv[BT * QKV];
__device__ float g_gu[BT * GU];

// ---------------- bf16 split activations ----------------
__device__ __nv_bfloat16 g_hh[BT * DD],  g_hl[BT * DD];    // rmsnorm out
__device__ __nv_bfloat16 g_qkvh[BT * QKV], g_qkvl[BT * QKV];
__device__ __nv_bfloat16 g_yh[BT * DD],  g_yl[BT * DD];    // attention out
__device__ __nv_bfloat16 g_ah[BT * II],  g_al[BT * II];    // silu*up out

// ---------------- bf16 split weights (prologue) ----------------
__device__ __nv_bfloat16 s_qkvw_h[NL * DD * QKV], s_qkvw_l[NL * DD * QKV];
__device__ __nv_bfloat16 s_ow_h[NL * DD * DD],    s_ow_l[NL * DD * DD];
__device__ __nv_bfloat16 s_guw_h[NL * DD * GU],   s_guw_l[NL * DD * GU];
__device__ __nv_bfloat16 s_dw_h[NL * II * DD],    s_dw_l[NL * II * DD];
__device__ __nv_bfloat16 s_em_h[(size_t)VV * DD], s_em_l[(size_t)VV * DD];

// ---------------- helpers ----------------
__device__ __forceinline__ void bf16_split(float v, __nv_bfloat16& h, __nv_bfloat16& l) {
    h = __float2bfloat16(v);
    l = __float2bfloat16(v - __bfloat162float(h));
}
__device__ __forceinline__ uint32_t packbf(__nv_bfloat16 a, __nv_bfloat16 b) {
    __nv_bfloat162 t = __halves2bfloat162(a, b);
    return *(uint32_t*)&t;
}
__device__ __forceinline__ void ldmx4(uint32_t* r, uint32_t a) {
    asm volatile("ldmatrix.sync.aligned.m8n8.x4.shared.b16 {%0,%1,%2,%3}, [%4];"
                 : "=r"(r[0]), "=r"(r[1]), "=r"(r[2]), "=r"(r[3]) : "r"(a));
}
__device__ __forceinline__ void ldmx4t(uint32_t* r, uint32_t a) {
    asm volatile("ldmatrix.sync.aligned.m8n8.x4.trans.shared.b16 {%0,%1,%2,%3}, [%4];"
                 : "=r"(r[0]), "=r"(r[1]), "=r"(r[2]), "=r"(r[3]) : "r"(a));
}
__device__ __forceinline__ void mma16816(float* c, const uint32_t* a, const uint32_t* b) {
    asm volatile("mma.sync.aligned.m16n8k16.row.col.f32.bf16.bf16.f32 "
                 "{%0,%1,%2,%3}, {%4,%5,%6,%7}, {%8,%9}, {%0,%1,%2,%3};"
                 : "+f"(c[0]), "+f"(c[1]), "+f"(c[2]), "+f"(c[3])
                 : "r"(a[0]), "r"(a[1]), "r"(a[2]), "r"(a[3]), "r"(b[0]), "r"(b[1]));
}
__device__ __forceinline__ void cpa16(uint32_t dst, const void* src) {
    asm volatile("cp.async.cg.shared.global [%0], [%1], 16;" :: "r"(dst), "l"(src));
}
__device__ __forceinline__ void cpcommit() { asm volatile("cp.async.commit_group;"); }
template<int N> __device__ __forceinline__ void cpwait() {
    asm volatile("cp.async.wait_group %0;" :: "n"(N));
}

// ---------------- fp32 -> bf16 hi/lo splitter ----------------
__global__ void split_kernel(const float* __restrict__ s,
                             __nv_bfloat16* __restrict__ h,
                             __nv_bfloat16* __restrict__ l, int n4) {
    int i = blockIdx.x * 256 + threadIdx.x;
    if (i >= n4) return;
    float4 v = ((const float4*)s)[i];
    __nv_bfloat16 h0, h1, h2, h3, l0, l1, l2, l3;
    bf16_split(v.x, h0, l0); bf16_split(v.y, h1, l1);
    bf16_split(v.z, h2, l2); bf16_split(v.w, h3, l3);
    __nv_bfloat162* hp = (__nv_bfloat162*)(h + (size_t)i * 4);
    __nv_bfloat162* lp = (__nv_bfloat162*)(l + (size_t)i * 4);
    hp[0] = __halves2bfloat162(h0, h1); hp[1] = __halves2bfloat162(h2, h3);
    lp[0] = __halves2bfloat162(l0, l1); lp[1] = __halves2bfloat162(l2, l3);
}

// ---------------- prologue: pack qkv weights [D][1152] ----------------
__global__ void pack_qkv4(const float* __restrict__ qw, const float* __restrict__ kw,
                          const float* __restrict__ vw) {
    int i4 = blockIdx.x * 256 + threadIdx.x;           // NL*DD*288
    int c4 = (i4 % 288) * 4;
    int rl = i4 / 288;
    int row = rl % DD, l = rl / DD;
    const float* src;
    if (c4 < DD)            src = qw + ((size_t)l * DD + row) * DD + c4;
    else if (c4 < DD + KVD) src = kw + ((size_t)l * DD + row) * KVD + (c4 - DD);
    else                    src = vw + ((size_t)l * DD + row) * KVD + (c4 - DD - KVD);
    float4 v = *(const float4*)src;
    __nv_bfloat16 h0, h1, h2, h3, l0, l1, l2, l3;
    bf16_split(v.x, h0, l0); bf16_split(v.y, h1, l1);
    bf16_split(v.z, h2, l2); bf16_split(v.w, h3, l3);
    __nv_bfloat162* hp = (__nv_bfloat162*)(s_qkvw_h + (size_t)i4 * 4);
    __nv_bfloat162* lp = (__nv_bfloat162*)(s_qkvw_l + (size_t)i4 * 4);
    hp[0] = __halves2bfloat162(h0, h1); hp[1] = __halves2bfloat162(h2, h3);
    lp[0] = __halves2bfloat162(l0, l1); lp[1] = __halves2bfloat162(l2, l3);
}

// ---------------- prologue: pack gate/up weights [D][4096] ----------------
__global__ void pack_gu4(const float* __restrict__ gw, const float* __restrict__ uw) {
    int i4 = blockIdx.x * 256 + threadIdx.x;           // NL*DD*1024
    int c4 = (i4 & 1023) * 4;
    int rl = i4 >> 10;
    int row = rl % DD, l = rl / DD;
    const float* src;
    if (c4 < II) src = gw + ((size_t)l * DD + row) * II + c4;
    else         src = uw + ((size_t)l * DD + row) * II + (c4 - II);
    float4 v = *(const float4*)src;
    __nv_bfloat16 h0, h1, h2, h3, l0, l1, l2, l3;
    bf16_split(v.x, h0, l0); bf16_split(v.y, h1, l1);
    bf16_split(v.z, h2, l2); bf16_split(v.w, h3, l3);
    __nv_bfloat162* hp = (__nv_bfloat162*)(s_guw_h + (size_t)i4 * 4);
    __nv_bfloat162* lp = (__nv_bfloat162*)(s_guw_l + (size_t)i4 * 4);
    hp[0] = __halves2bfloat162(h0, h1); hp[1] = __halves2bfloat162(h2, h3);
    lp[0] = __halves2bfloat162(l0, l1); lp[1] = __halves2bfloat162(l2, l3);
}

// ---------------- embedding gather ----------------
__global__ void embed_kernel(const int* __restrict__ idx,
                             const float* __restrict__ embed) {
    int row = blockIdx.x;
    int t4  = threadIdx.x;
    const float4* src = (const float4*)(embed + (size_t)idx[row] * DD);
    ((float4*)(g_x + (size_t)row * DD))[t4] = src[t4];
}

// ---------------- RMSNorm -> bf16 hi/lo ----------------
__global__ __launch_bounds__(256) void rmsnorm_split(const float* __restrict__ in,
                                                     const float* __restrict__ w,
                                                     __nv_bfloat16* __restrict__ oh,
                                                     __nv_bfloat16* __restrict__ ol) {
    int row = blockIdx.x;
    const float* x = in + (size_t)row * DD;
    float s = 0.f;
    for (int i = threadIdx.x; i < DD; i += 256) { float v = x[i]; s += v * v; }
    #pragma unroll
    for (int o = 16; o; o >>= 1) s += __shfl_xor_sync(0xffffffffu, s, o);
    __shared__ float red[8];
    if ((threadIdx.x & 31) == 0) red[threadIdx.x >> 5] = s;
    __syncthreads();
    if (threadIdx.x < 8) {
        s = red[threadIdx.x];
        #pragma unroll
        for (int o = 4; o; o >>= 1) s += __shfl_xor_sync(0xffu, s, o);
        if (threadIdx.x == 0) red[0] = s;
    }
    __syncthreads();
    float inv = rsqrtf(red[0] / (float)DD + EPS_);
    for (int i = threadIdx.x; i < DD; i += 256) {
        float r = w[i] * x[i] * inv;
        __nv_bfloat16 h, l;
        bf16_split(r, h, l);
        oh[(size_t)row * DD + i] = h;
        ol[(size_t)row * DD + i] = l;
    }
}

// ---------------- bf16x3 tensor-core GEMM, cp.async double-buffered ----------------
// C[M,N] = A[M,K] @ B (+C if ACCUM). TRANSB==0: B[K,N]; TRANSB==1: B[N,K].
// Block tile 128x128, BK=32, 2 stages. 8 warps 2x4, warp tile 64x32.
template<int TRANSB, int ACCUM>
__global__ __launch_bounds__(256) void bgemm(const __nv_bfloat16* __restrict__ Ah,
                                             const __nv_bfloat16* __restrict__ Al,
                                             const __nv_bfloat16* __restrict__ Bh,
                                             const __nv_bfloat16* __restrict__ Bl,
                                             float* __restrict__ C,
                                             int M, int N, int K) {
    constexpr int AST   = 40;
    constexpr int BROWS = TRANSB ? 128 : 32;
    constexpr int BST   = TRANSB ? 40  : 136;
    constexpr int ASZ   = 128 * AST;
    constexpr int BSZ   = BROWS * BST;
    constexpr int STG   = 2 * ASZ + 2 * BSZ;      // elems per stage

    extern __shared__ __nv_bfloat16 smem[];
    int tid  = threadIdx.x;
    int lane = tid & 31, wid = tid >> 5;
    int wm = wid >> 2, wn = wid & 3;
    int row0 = blockIdx.y * 128, col0 = blockIdx.x * 128;

    float c[4][4][4] = {};
    uint32_t sbase = (uint32_t)__cvta_generic_to_shared(smem);

    int am = tid >> 2, aq = (tid & 3) * 8;

    auto load_stage = [&](int st, int k0) {
        uint32_t aoff = sbase + (uint32_t)st * STG * 2;
        #pragma unroll
        for (int i = 0; i < 2; i++) {
            int m = am + i * 64;
            size_t g = (size_t)(row0 + m) * K + k0 + aq;
            cpa16(aoff + (m * AST + aq) * 2, Ah + g);
            cpa16(aoff + (ASZ + m * AST + aq) * 2, Al + g);
        }
        uint32_t boff = aoff + 2 * ASZ * 2;
        if (!TRANSB) {
            #pragma unroll
            for (int i = 0; i < 2; i++) {
                int k = (tid >> 4) + i * 16, q = (tid & 15) * 8;
                size_t g = (size_t)(k0 + k) * N + col0 + q;   // N % 128 == 0 here
                cpa16(boff + (k * BST + q) * 2, Bh + g);
                cpa16(boff + (BSZ + k * BST + q) * 2, Bl + g);
            }
        } else {
            #pragma unroll
            for (int i = 0; i < 2; i++) {
                int n = (tid >> 2) + i * 64, q = (tid & 3) * 8;
                if (col0 + n < N) {
                    size_t g = (size_t)(col0 + n) * K + k0 + q;
                    cpa16(boff + (n * BST + q) * 2, Bh + g);
                    cpa16(boff + (BSZ + n * BST + q) * 2, Bl + g);
                }
            }
        }
    };

    int nit = K / 32;
    load_stage(0, 0);
    cpcommit();

    for (int it = 0; it < nit; it++) {
        int cur = it & 1;
        if (it + 1 < nit) { load_stage(cur ^ 1, (it + 1) * 32); cpcommit(); cpwait<1>(); }
        else              { cpwait<0>(); }
        __syncthreads();

        uint32_t sA   = sbase + (uint32_t)cur * STG * 2;
        uint32_t sAl_ = sA + ASZ * 2;
        uint32_t sB   = sA + 2 * ASZ * 2;
        uint32_t sBl_ = sB + BSZ * 2;

        #pragma unroll
        for (int kk = 0; kk < 32; kk += 16) {
            uint32_t fah[4][4], fal[4][4], fbh[2][4], fbl[2][4];
            int abase = ((wm * 64 + (lane & 15)) * AST + (lane >> 4) * 8 + kk) * 2;
            #pragma unroll
            for (int mf = 0; mf < 4; mf++) {
                ldmx4(fah[mf], sA   + abase + mf * 16 * AST * 2);
                ldmx4(fal[mf], sAl_ + abase + mf * 16 * AST * 2);
            }
            if (!TRANSB) {
                int bbase = (((lane & 7) + ((lane >> 3) & 1) * 8 + kk) * BST
                             + wn * 32 + ((lane >> 4) & 1) * 8) * 2;
                ldmx4t(fbh[0], sB + bbase);   ldmx4t(fbh[1], sB + bbase + 32);
                ldmx4t(fbl[0], sBl_ + bbase); ldmx4t(fbl[1], sBl_ + bbase + 32);
            } else {
                int bbase = ((wn * 32 + (lane & 7) + ((lane >> 4) & 1) * 8) * BST
                             + ((lane >> 3) & 1) * 8 + kk) * 2;
                ldmx4(fbh[0], sB + bbase);   ldmx4(fbh[1], sB + bbase + 16 * BST * 2);
                ldmx4(fbl[0], sBl_ + bbase); ldmx4(fbl[1], sBl_ + bbase + 16 * BST * 2);
            }
            #pragma unroll
            for (int mf = 0; mf < 4; mf++)
                #pragma unroll
                for (int nf = 0; nf < 4; nf++) {
                    const uint32_t* bh2 = &fbh[nf >> 1][(nf & 1) * 2];
                    const uint32_t* bl2 = &fbl[nf >> 1][(nf & 1) * 2];
                    mma16816(c[mf][nf], fah[mf], bh2);
                    mma16816(c[mf][nf], fah[mf], bl2);
                    mma16816(c[mf][nf], fal[mf], bh2);
                }
        }
        __syncthreads();
    }

    int g = lane >> 2, t = lane & 3;
    #pragma unroll
    for (int mf = 0; mf < 4; mf++) {
        #pragma unroll
        for (int nf = 0; nf < 4; nf++) {
            int r  = row0 + wm * 64 + mf * 16 + g;
            int cc = col0 + wn * 32 + nf * 8 + t * 2;
            float* p0 = C + (size_t)r * N + cc;
            float* p1 = C + (size_t)(r + 8) * N + cc;
            if (cc < N) {
                if (ACCUM) { p0[0] += c[mf][nf][0]; p1[0] += c[mf][nf][2]; }
                else       { p0[0]  = c[mf][nf][0]; p1[0]  = c[mf][nf][2]; }
            }
            if (cc + 1 < N) {
                if (ACCUM) { p0[1] += c[mf][nf][1]; p1[1] += c[mf][nf][3]; }
                else       { p0[1]  = c[mf][nf][1]; p1[1]  = c[mf][nf][3]; }
            }
        }
    }
}

// ---------------- RoPE in fused qkv buffer; q scaled by 1/sqrt(HS) ----------------
__global__ void rope_kernel() {
    int row = blockIdx.x;
    int t = row % TT;
    int i = threadIdx.x;                 // 480 = (12+3)*32
    int head = i >> 5;
    int d = i & 31;
    float freq = powf(10000.f, (float)d / 32.0f);
    float ang = (float)t / freq;
    float s, c;
    sincosf(ang, &s, &c);
    float* p;
    float sc;
    if (head < HH) { p = g_qkv + (size_t)row * QKV + head * HS;                sc = 0.125f; }
    else           { p = g_qkv + (size_t)row * QKV + DD + (head - HH) * HS;    sc = 1.0f;   }
    float xr = p[d], xi = p[d + 32];
    p[d]      = (xr * c - xi * s) * sc;
    p[d + 32] = (xi * c + xr * s) * sc;
}

// ---------------- flash attention, bf16x3 mma, 128-query tiles ----------------
// grid (TT/128, B*HH), 256 threads (8 warps; warp w owns rows w*16..w*16+15)
#define AT_ST 72
#define ATN_SMEM ((2 * 128 * AT_ST + 4 * 64 * AT_ST) * 2)   // bytes

__global__ __launch_bounds__(256) void attn_mma() {
    extern __shared__ __nv_bfloat16 sm[];
    __nv_bfloat16* Qh = sm;
    __nv_bfloat16* Ql = Qh + 128 * AT_ST;
    __nv_bfloat16* Kh = Ql + 128 * AT_ST;
    __nv_bfloat16* Kl = Kh + 64 * AT_ST;
    __nv_bfloat16* Vh = Kl + 64 * AT_ST;
    __nv_bfloat16* Vl = Vh + 64 * AT_ST;

    int tid = threadIdx.x, lane = tid & 31, w = tid >> 5;
    int q0 = blockIdx.x * 128;
    int b = blockIdx.y / HH, h = blockIdx.y % HH, kvh = h % NKV;

    uint32_t sQh = (uint32_t)__cvta_generic_to_shared(Qh);
    uint32_t sQl = (uint32_t)__cvta_generic_to_shared(Ql);
    uint32_t sKh = (uint32_t)__cvta_generic_to_shared(Kh);
    uint32_t sKl = (uint32_t)__cvta_generic_to_shared(Kl);
    uint32_t sVh = (uint32_t)__cvta_generic_to_shared(Vh);
    uint32_t sVl = (uint32_t)__cvta_generic_to_shared(Vl);

    // load Q tile (already scaled by 0.125 in rope)
    for (int i = tid; i < 128 * 8; i += 256) {
        int row = i >> 3, q8 = (i & 7) * 8;
        size_t g = (size_t)(b * TT + q0 + row) * QKV + h * HS + q8;
        *(uint4*)&Qh[row * AT_ST + q8] = *(const uint4*)&g_qkvh[g];
        *(uint4*)&Ql[row * AT_ST + q8] = *(const uint4*)&g_qkvl[g];
    }
    __syncthreads();

    uint32_t qfh[4][4], qfl[4][4];
    {
        int abase = ((w * 16 + (lane & 15)) * AT_ST + (lane >> 4) * 8) * 2;
        #pragma unroll
        for (int kp = 0; kp < 4; kp++) {
            ldmx4(qfh[kp], sQh + abase + kp * 32);
            ldmx4(qfl[kp], sQl + abase + kp * 32);
        }
    }

    float m0 = -1e30f, m1 = -1e30f, l0 = 0.f, l1 = 0.f;
    float co[8][4] = {};
    int r_seq = q0 + w * 16 + (lane >> 2);
    int nt = q0 / 64 + 2;

    for (int it = 0; it < nt; it++) {
        int s0 = it * 64;
        __syncthreads();
        for (int i = tid; i < 64 * 8; i += 256) {
            int row = i >> 3, q8 = (i & 7) * 8;
            size_t gk = (size_t)(b * TT + s0 + row) * QKV + DD + kvh * HS + q8;
            size_t gv = gk + KVD;
            *(uint4*)&Kh[row * AT_ST + q8] = *(const uint4*)&g_qkvh[gk];
            *(uint4*)&Kl[row * AT_ST + q8] = *(const uint4*)&g_qkvl[gk];
            *(uint4*)&Vh[row * AT_ST + q8] = *(const uint4*)&g_qkvh[gv];
            *(uint4*)&Vl[row * AT_ST + q8] = *(const uint4*)&g_qkvl[gv];
        }
        __syncthreads();

        // S = Q K^T  (keys as n, dims as k) — TRANSB=1 fragment pattern
        float cs[8][4] = {};
        #pragma unroll
        for (int kp = 0; kp < 4; kp++) {
            #pragma unroll
            for (int ng = 0; ng < 4; ng++) {
                uint32_t bh[4], bl[4];
                int bbase = ((ng * 16 + (lane & 7) + ((lane >> 4) & 1) * 8) * AT_ST
                             + ((lane >> 3) & 1) * 8 + kp * 16) * 2;
                ldmx4(bh, sKh + bbase);
                ldmx4(bl, sKl + bbase);
                mma16816(cs[2 * ng],     qfh[kp], &bh[0]);
                mma16816(cs[2 * ng],     qfh[kp], &bl[0]);
                mma16816(cs[2 * ng],     qfl[kp], &bh[0]);
                mma16816(cs[2 * ng + 1], qfh[kp], &bh[2]);
                mma16816(cs[2 * ng + 1], qfh[kp], &bl[2]);
                mma16816(cs[2 * ng + 1], qfl[kp], &bh[2]);
            }
        }

        // causal mask (only tiles that can intersect the diagonal of this warp)
        if (s0 + 63 > q0 + w * 16) {
            #pragma unroll
            for (int nf = 0; nf < 8; nf++) {
                int key = s0 + nf * 8 + (lane & 3) * 2;
                if (key     > r_seq)     cs[nf][0] = -1e30f;
                if (key + 1 > r_seq)     cs[nf][1] = -1e30f;
                if (key     > r_seq + 8) cs[nf][2] = -1e30f;
                if (key + 1 > r_seq + 8) cs[nf][3] = -1e30f;
            }
        }

        // online softmax over 2 rows per thread
        float mx0 = cs[0][0], mx1 = cs[0][2];
        #pragma unroll
        for (int nf = 0; nf < 8; nf++) {
            mx0 = fmaxf(mx0, fmaxf(cs[nf][0], cs[nf][1]));
            mx1 = fmaxf(mx1, fmaxf(cs[nf][2], cs[nf][3]));
        }
        mx0 = fmaxf(mx0, __shfl_xor_sync(0xffffffffu, mx0, 1));
        mx0 = fmaxf(mx0, __shfl_xor_sync(0xffffffffu, mx0, 2));
        mx1 = fmaxf(mx1, __shfl_xor_sync(0xffffffffu, mx1, 1));
        mx1 = fmaxf(mx1, __shfl_xor_sync(0xffffffffu, mx1, 2));
        float nm0 = fmaxf(m0, mx0), nm1 = fmaxf(m1, mx1);
        float corr0 = __expf(m0 - nm0), corr1 = __expf(m1 - nm1);
        m0 = nm0; m1 = nm1;

        uint32_t pfh[4][4], pfl[4][4];
        float sum0 = 0.f, sum1 = 0.f;
        #pragma unroll
        for (int nf = 0; nf < 8; nf++) {
            float p0 = __expf(cs[nf][0] - nm0), p1 = __expf(cs[nf][1] - nm0);
            float p2 = __expf(cs[nf][2] - nm1), p3 = __expf(cs[nf][3] - nm1);
            sum0 += p0 + p1; sum1 += p2 + p3;
            __nv_bfloat16 h0, lo0, h1, lo1, h2, lo2, h3, lo3;
            bf16_split(p0, h0, lo0); bf16_split(p1, h1, lo1);
            bf16_split(p2, h2, lo2); bf16_split(p3, h3, lo3);
            int kp = nf >> 1, o = (nf & 1) * 2;
            pfh[kp][o]     = packbf(h0, h1);  pfh[kp][o + 1] = packbf(h2, h3);
            pfl[kp][o]     = packbf(lo0, lo1); pfl[kp][o + 1] = packbf(lo2, lo3);
        }
        sum0 += __shfl_xor_sync(0xffffffffu, sum0, 1);
        sum0 += __shfl_xor_sync(0xffffffffu, sum0, 2);
        sum1 += __shfl_xor_sync(0xffffffffu, sum1, 1);
        sum1 += __shfl_xor_sync(0xffffffffu, sum1, 2);
        l0 = l0 * corr0 + sum0;
        l1 = l1 * corr1 + sum1;
        #pragma unroll
        for (int nf = 0; nf < 8; nf++) {
            co[nf][0] *= corr0; co[nf][1] *= corr0;
            co[nf][2] *= corr1; co[nf][3] *= corr1;
        }

        // O += P V  (keys as k, dims as n) — TRANSB=0 fragment pattern
        #pragma unroll
        for (int kp = 0; kp < 4; kp++) {
            #pragma unroll
            for (int ng = 0; ng < 4; ng++) {
                uint32_t bh[4], bl[4];
                int bbase = (((lane & 7) + ((lane >> 3) & 1) * 8 + kp * 16) * AT_ST
                             + ng * 16 + ((lane >> 4) & 1) * 8) * 2;
                ldmx4t(bh, sVh + bbase);
                ldmx4t(bl, sVl + bbase);
                mma16816(co[2 * ng],     pfh[kp], &bh[0]);
                mma16816(co[2 * ng],     pfh[kp], &bl[0]);
                mma16816(co[2 * ng],     pfl[kp], &bh[0]);
                mma16816(co[2 * ng + 1], pfh[kp], &bh[2]);
                mma16816(co[2 * ng + 1], pfh[kp], &bl[2]);
                mma16816(co[2 * ng + 1], pfl[kp], &bh[2]);
            }
        }
    }

    float il0 = 1.f / l0, il1 = 1.f / l1;
    size_t base0 = (size_t)(b * TT + r_seq) * DD + h * HS;
    size_t base1 = base0 + (size_t)8 * DD;
    #pragma unroll
    for (int nf = 0; nf < 8; nf++) {
        int cc = nf * 8 + (lane & 3) * 2;
        float y0 = co[nf][0] * il0, y1 = co[nf][1] * il0;
        float y2 = co[nf][2] * il1, y3 = co[nf][3] * il1;
        __nv_bfloat16 h0, lo0, h1, lo1, h2, lo2, h3, lo3;
        bf16_split(y0, h0, lo0); bf16_split(y1, h1, lo1);
        bf16_split(y2, h2, lo2); bf16_split(y3, h3, lo3);
        *(__nv_bfloat162*)&g_yh[base0 + cc] = __halves2bfloat162(h0, h1);
        *(__nv_bfloat162*)&g_yl[base0 + cc] = __halves2bfloat162(lo0, lo1);
        *(__nv_bfloat162*)&g_yh[base1 + cc] = __halves2bfloat162(h2, h3);
        *(__nv_bfloat162*)&g_yl[base1 + cc] = __halves2bfloat162(lo2, lo3);
    }
}

// ---------------- SiLU(gate) * up -> bf16 hi/lo (float4) ----------------
__global__ void silu_mul_kernel() {
    int i4 = blockIdx.x * 256 + threadIdx.x;     // BT*II/4
    int row = i4 >> 9;
    int col = (i4 & 511) * 4;
    float4 gv = *(const float4*)&g_gu[(size_t)row * GU + col];
    float4 uv = *(const float4*)&g_gu[(size_t)row * GU + II + col];
    float r0 = gv.x / (1.f + __expf(-gv.x)) * uv.x;
    float r1 = gv.y / (1.f + __expf(-gv.y)) * uv.y;
    float r2 = gv.z / (1.f + __expf(-gv.z)) * uv.z;
    float r3 = gv.w / (1.f + __expf(-gv.w)) * uv.w;
    __nv_bfloat16 h0, l0, h1, l1, h2, l2, h3, l3;
    bf16_split(r0, h0, l0); bf16_split(r1, h1, l1);
    bf16_split(r2, h2, l2); bf16_split(r3, h3, l3);
    size_t o = (size_t)row * II + col;
    *(__nv_bfloat162*)&g_ah[o]     = __halves2bfloat162(h0, h1);
    *(__nv_bfloat162*)&g_ah[o + 2] = __halves2bfloat162(h2, h3);
    *(__nv_bfloat162*)&g_al[o]     = __halves2bfloat162(l0, l1);
    *(__nv_bfloat162*)&g_al[o + 2] = __halves2bfloat162(l2, l3);
}

// ---------------- host ----------------
static inline int sgrid(size_t n4) { return (int)((n4 + 255) / 256); }

extern "C" void kernel_launch(void* const* d_in, const int* in_sizes, int n_in,
                              void* d_out, int out_size) {
    const int*   idx   = (const int*)d_in[0];
    const float* embed = (const float*)d_in[1];
    const float* ln1   = (const float*)d_in[2];
    const float* qw    = (const float*)d_in[3];
    const float* kw    = (const float*)d_in[4];
    const float* vw    = (const float*)d_in[5];
    const float* ow    = (const float*)d_in[6];
    const float* ln2   = (const float*)d_in[7];
    const float* gw    = (const float*)d_in[8];
    const float* uw    = (const float*)d_in[9];
    const float* dw    = (const float*)d_in[10];
    const float* nw    = (const float*)d_in[11];
    float* out = (float*)d_out;

    float *px, *pqkv, *pgu;
    cudaGetSymbolAddress((void**)&px,   g_x);
    cudaGetSymbolAddress((void**)&pqkv, g_qkv);
    cudaGetSymbolAddress((void**)&pgu,  g_gu);

    __nv_bfloat16 *hh, *hl, *yh, *yl, *ah, *al, *qvh, *qvl;
    cudaGetSymbolAddress((void**)&hh,  g_hh);  cudaGetSymbolAddress((void**)&hl,  g_hl);
    cudaGetSymbolAddress((void**)&yh,  g_yh);  cudaGetSymbolAddress((void**)&yl,  g_yl);
    cudaGetSymbolAddress((void**)&ah,  g_ah);  cudaGetSymbolAddress((void**)&al,  g_al);
    cudaGetSymbolAddress((void**)&qvh, g_qkvh); cudaGetSymbolAddress((void**)&qvl, g_qkvl);

    __nv_bfloat16 *qkvwh, *qkvwl, *owh, *owl, *guwh, *guwl, *dwh, *dwl, *emh, *eml;
    cudaGetSymbolAddress((void**)&qkvwh, s_qkvw_h); cudaGetSymbolAddress((void**)&qkvwl, s_qkvw_l);
    cudaGetSymbolAddress((void**)&owh, s_ow_h);     cudaGetSymbolAddress((void**)&owl, s_ow_l);
    cudaGetSymbolAddress((void**)&guwh, s_guw_h);   cudaGetSymbolAddress((void**)&guwl, s_guw_l);
    cudaGetSymbolAddress((void**)&dwh, s_dw_h);     cudaGetSymbolAddress((void**)&dwl, s_dw_l);
    cudaGetSymbolAddress((void**)&emh, s_em_h);     cudaGetSymbolAddress((void**)&eml, s_em_l);

    // dynamic smem opt-in
    const int SM_G0 = (2 * (128 * 40) + 2 * (32 * 136)) * 2 * 2;   // 75776 B
    const int SM_G1 = (2 * (128 * 40) + 2 * (128 * 40)) * 2 * 2;   // 81920 B
    cudaFuncSetAttribute(bgemm<0, 0>, cudaFuncAttributeMaxDynamicSharedMemorySize, SM_G0);
    cudaFuncSetAttribute(bgemm<0, 1>, cudaFuncAttributeMaxDynamicSharedMemorySize, SM_G0);
    cudaFuncSetAttribute(bgemm<1, 0>, cudaFuncAttributeMaxDynamicSharedMemorySize, SM_G1);
    cudaFuncSetAttribute(attn_mma,    cudaFuncAttributeMaxDynamicSharedMemorySize, ATN_SMEM);

    // ---- prologue: pack/split weights ----
    pack_qkv4<<<NL * DD * 288 / 256, 256>>>(qw, kw, vw);
    pack_gu4 <<<NL * DD * 1024 / 256, 256>>>(gw, uw);
    split_kernel<<<sgrid((size_t)NL * DD * DD / 4), 256>>>(ow, owh, owl, NL * DD * DD / 4);
    split_kernel<<<sgrid((size_t)NL * II * DD / 4), 256>>>(dw, dwh, dwl, NL * II * DD / 4);
    split_kernel<<<sgrid((size_t)VV * DD / 4), 256>>>(embed, emh, eml, VV * DD / 4);

    dim3 gqkv(QKV / 128, BT / 128);        // (9,16)
    dim3 go(DD / 128, BT / 128);           // (6,16)
    dim3 ggu(GU / 128, BT / 128);          // (32,16)
    dim3 ga(TT / 128, 2 * HH);             // (8,24)
    dim3 gl((VV + 127) / 128, BT / 128);   // (393,16)

    embed_kernel<<<BT, 192>>>(idx, embed);

    for (int l = 0; l < NL; l++) {
        size_t oQ = (size_t)l * DD * QKV;
        size_t oO = (size_t)l * DD * DD;
        size_t oG = (size_t)l * DD * GU;
        size_t oD2 = (size_t)l * II * DD;

        rmsnorm_split<<<BT, 256>>>(px, ln1 + (size_t)l * DD, hh, hl);
        bgemm<0, 0><<<gqkv, 256, SM_G0>>>(hh, hl, qkvwh + oQ, qkvwl + oQ, pqkv, BT, QKV, DD);
        rope_kernel<<<BT, 480>>>();
        split_kernel<<<sgrid((size_t)BT * QKV / 4), 256>>>(pqkv, qvh, qvl, BT * QKV / 4);
        attn_mma<<<ga, 256, ATN_SMEM>>>();
        bgemm<0, 1><<<go, 256, SM_G0>>>(yh, yl, owh + oO, owl + oO, px, BT, DD, DD);
        rmsnorm_split<<<BT, 256>>>(px, ln2 + (size_t)l * DD, hh, hl);
        bgemm<0, 0><<<ggu, 256, SM_G0>>>(hh, hl, guwh + oG, guwl + oG, pgu, BT, GU, DD);
        silu_mul_kernel<<<BT * II / 4 / 256, 256>>>();
        bgemm<0, 1><<<go, 256, SM_G0>>>(ah, al, dwh + oD2, dwl + oD2, px, BT, DD, II);
    }

    rmsnorm_split<<<BT, 256>>>(px, nw, hh, hl);
    bgemm<1, 0><<<gl, 256, SM_G1>>>(hh, hl, emh, eml, out, BT, VV, DD);
}

// round 10
// speedup vs baseline: 1.0001x; 1.0001x over previous
#include <cuda_runtime.h>
#include <cuda_bf16.h>
#include <math.h>
#include <stdint.h>

#define BT   2048
#define TT   1024
#define DD   768
#define HH   12
#define HS   64
#define NKV  3
#define NL   12
#define II   2048
#define VV   50257
#define KVD  192
#define QKV  1152
#define GU   4096
#define EPS_ 1e-6f

// fp32 scratch
__device__ float g_x[BT * DD];
__device__ float g_qkv[BT * QKV];
__device__ float g_gu[BT * GU];
// bf16 split activations
__device__ __nv_bfloat16 g_hh[BT * DD],  g_hl[BT * DD];
__device__ __nv_bfloat16 g_qkvh[BT * QKV], g_qkvl[BT * QKV];
__device__ __nv_bfloat16 g_yh[BT * DD],  g_yl[BT * DD];
__device__ __nv_bfloat16 g_ah[BT * II],  g_al[BT * II];
// bf16 split weights ([K][N] layout for TRANSB=0 GEMMs)
__device__ __nv_bfloat16 s_qkvw_h[NL * DD * QKV], s_qkvw_l[NL * DD * QKV];
__device__ __nv_bfloat16 s_ow_h[NL * DD * DD],    s_ow_l[NL * DD * DD];
__device__ __nv_bfloat16 s_guw_h[NL * DD * GU],   s_guw_l[NL * DD * GU];
__device__ __nv_bfloat16 s_dw_h[NL * II * DD],    s_dw_l[NL * II * DD];
__device__ __nv_bfloat16 s_em_h[(size_t)VV * DD], s_em_l[(size_t)VV * DD];

__device__ __forceinline__ void bf16_split(float v, __nv_bfloat16& h, __nv_bfloat16& l) {
    h = __float2bfloat16(v);
    l = __float2bfloat16(v - __bfloat162float(h));
}
__device__ __forceinline__ uint32_t packbf(__nv_bfloat16 a, __nv_bfloat16 b) {
    __nv_bfloat162 t = __halves2bfloat162(a, b);
    return *(uint32_t*)&t;
}
__device__ __forceinline__ void ldmx4(uint32_t* r, uint32_t a) {
    asm volatile("ldmatrix.sync.aligned.m8n8.x4.shared.b16 {%0,%1,%2,%3}, [%4];"
                 : "=r"(r[0]), "=r"(r[1]), "=r"(r[2]), "=r"(r[3]) : "r"(a));
}
__device__ __forceinline__ void ldmx4t(uint32_t* r, uint32_t a) {
    asm volatile("ldmatrix.sync.aligned.m8n8.x4.trans.shared.b16 {%0,%1,%2,%3}, [%4];"
                 : "=r"(r[0]), "=r"(r[1]), "=r"(r[2]), "=r"(r[3]) : "r"(a));
}
__device__ __forceinline__ void mma16816(float* c, const uint32_t* a, const uint32_t* b) {
    asm volatile("mma.sync.aligned.m16n8k16.row.col.f32.bf16.bf16.f32 "
                 "{%0,%1,%2,%3}, {%4,%5,%6,%7}, {%8,%9}, {%0,%1,%2,%3};"
                 : "+f"(c[0]), "+f"(c[1]), "+f"(c[2]), "+f"(c[3])
                 : "r"(a[0]), "r"(a[1]), "r"(a[2]), "r"(a[3]), "r"(b[0]), "r"(b[1]));
}
__device__ __forceinline__ void cpa16(uint32_t dst, const void* src) {
    asm volatile("cp.async.cg.shared.global [%0], [%1], 16;" :: "r"(dst), "l"(src));
}
__device__ __forceinline__ void cpcommit() { asm volatile("cp.async.commit_group;"); }
template<int N> __device__ __forceinline__ void cpwait() {
    asm volatile("cp.async.wait_group %0;" :: "n"(N));
}

// fp32 -> bf16 hi/lo splitter
__global__ void split_kernel(const float* __restrict__ s, __nv_bfloat16* __restrict__ h,
                             __nv_bfloat16* __restrict__ l, int n4) {
    int i = blockIdx.x * 256 + threadIdx.x;
    if (i >= n4) return;
    float4 v = ((const float4*)s)[i];
    __nv_bfloat16 h0, h1, h2, h3, l0, l1, l2, l3;
    bf16_split(v.x, h0, l0); bf16_split(v.y, h1, l1);
    bf16_split(v.z, h2, l2); bf16_split(v.w, h3, l3);
    __nv_bfloat162* hp = (__nv_bfloat162*)(h + (size_t)i * 4);
    __nv_bfloat162* lp = (__nv_bfloat162*)(l + (size_t)i * 4);
    hp[0] = __halves2bfloat162(h0, h1); hp[1] = __halves2bfloat162(h2, h3);
    lp[0] = __halves2bfloat162(l0, l1); lp[1] = __halves2bfloat162(l2, l3);
}

// pack qkv weights -> [D][1152]
__global__ void pack_qkv4(const float* __restrict__ qw, const float* __restrict__ kw,
                          const float* __restrict__ vw) {
    int i4 = blockIdx.x * 256 + threadIdx.x;
    int c4 = (i4 % 288) * 4;
    int rl = i4 / 288;
    int row = rl % DD, l = rl / DD;
    const float* src;
    if (c4 < DD)            src = qw + ((size_t)l * DD + row) * DD + c4;
    else if (c4 < DD + KVD) src = kw + ((size_t)l * DD + row) * KVD + (c4 - DD);
    else                    src = vw + ((size_t)l * DD + row) * KVD + (c4 - DD - KVD);
    float4 v = *(const float4*)src;
    __nv_bfloat16 h0, h1, h2, h3, l0, l1, l2, l3;
    bf16_split(v.x, h0, l0); bf16_split(v.y, h1, l1);
    bf16_split(v.z, h2, l2); bf16_split(v.w, h3, l3);
    __nv_bfloat162* hp = (__nv_bfloat162*)(s_qkvw_h + (size_t)i4 * 4);
    __nv_bfloat162* lp = (__nv_bfloat162*)(s_qkvw_l + (size_t)i4 * 4);
    hp[0] = __halves2bfloat162(h0, h1); hp[1] = __halves2bfloat162(h2, h3);
    lp[0] = __halves2bfloat162(l0, l1); lp[1] = __halves2bfloat162(l2, l3);
}

// pack gate/up weights -> [D][4096]
__global__ void pack_gu4(const float* __restrict__ gw, const float* __restrict__ uw) {
    int i4 = blockIdx.x * 256 + threadIdx.x;
    int c4 = (i4 & 1023) * 4;
    int rl = i4 >> 10;
    int row = rl % DD, l = rl / DD;
    const float* src;
    if (c4 < II) src = gw + ((size_t)l * DD + row) * II + c4;
    else         src = uw + ((size_t)l * DD + row) * II + (c4 - II);
    float4 v = *(const float4*)src;
    __nv_bfloat16 h0, h1, h2, h3, l0, l1, l2, l3;
    bf16_split(v.x, h0, l0); bf16_split(v.y, h1, l1);
    bf16_split(v.z, h2, l2); bf16_split(v.w, h3, l3);
    __nv_bfloat162* hp = (__nv_bfloat162*)(s_guw_h + (size_t)i4 * 4);
    __nv_bfloat162* lp = (__nv_bfloat162*)(s_guw_l + (size_t)i4 * 4);
    hp[0] = __halves2bfloat162(h0, h1); hp[1] = __halves2bfloat162(h2, h3);
    lp[0] = __halves2bfloat162(l0, l1); lp[1] = __halves2bfloat162(l2, l3);
}

__global__ void embed_kernel(const int* __restrict__ idx, const float* __restrict__ embed) {
    int row = blockIdx.x;
    const float4* src = (const float4*)(embed + (size_t)idx[row] * DD);
    ((float4*)(g_x + (size_t)row * DD))[threadIdx.x] = src[threadIdx.x];
}

__global__ __launch_bounds__(256) void rmsnorm_split(const float* __restrict__ in,
                                                     const float* __restrict__ w,
                                                     __nv_bfloat16* __restrict__ oh,
                                                     __nv_bfloat16* __restrict__ ol) {
    int row = blockIdx.x;
    const float* x = in + (size_t)row * DD;
    float s = 0.f;
    for (int i = threadIdx.x; i < DD; i += 256) { float v = x[i]; s += v * v; }
    #pragma unroll
    for (int o = 16; o; o >>= 1) s += __shfl_xor_sync(0xffffffffu, s, o);
    __shared__ float red[8];
    if ((threadIdx.x & 31) == 0) red[threadIdx.x >> 5] = s;
    __syncthreads();
    if (threadIdx.x < 8) {
        s = red[threadIdx.x];
        #pragma unroll
        for (int o = 4; o; o >>= 1) s += __shfl_xor_sync(0xffu, s, o);
        if (threadIdx.x == 0) red[0] = s;
    }
    __syncthreads();
    float inv = rsqrtf(red[0] / (float)DD + EPS_);
    for (int i = threadIdx.x; i < DD; i += 256) {
        float r = w[i] * x[i] * inv;
        __nv_bfloat16 h, l;
        bf16_split(r, h, l);
        oh[(size_t)row * DD + i] = h;
        ol[(size_t)row * DD + i] = l;
    }
}

// ---------------- bf16x3 mma.sync GEMM, 3-stage cp.async pipeline ----------------
// C[M,N] = A[M,K] @ B (+C if ACCUM). TRANSB==0: B[K,N]; TRANSB==1: B[N,K].
// SPLITK: blockIdx.z sub-range of K; epilogue uses atomicAdd (requires ACCUM semantics).
// MSWAP: row tile from blockIdx.x (m-fastest, for L2 B-reuse on the LM head).
template<int TRANSB, int ACCUM, int SPLITK, int MSWAP>
__global__ __launch_bounds__(256) void bgemm(const __nv_bfloat16* __restrict__ Ah,
                                             const __nv_bfloat16* __restrict__ Al,
                                             const __nv_bfloat16* __restrict__ Bh,
                                             const __nv_bfloat16* __restrict__ Bl,
                                             float* __restrict__ C,
                                             int M, int N, int K) {
    constexpr int AST   = 40;
    constexpr int BROWS = TRANSB ? 128 : 32;
    constexpr int BST   = TRANSB ? 40  : 136;
    constexpr int ASZ   = 128 * AST;
    constexpr int BSZ   = BROWS * BST;
    constexpr int STG   = 2 * ASZ + 2 * BSZ;
    constexpr int NSTG  = 3;

    extern __shared__ __nv_bfloat16 smem[];
    int tid  = threadIdx.x;
    int lane = tid & 31, wid = tid >> 5;
    int wm = wid >> 2, wn = wid & 3;
    int row0 = (MSWAP ? blockIdx.x : blockIdx.y) * 128;
    int col0 = (MSWAP ? blockIdx.y : blockIdx.x) * 128;
    int kbeg = SPLITK > 1 ? blockIdx.z * (K / SPLITK) : 0;
    int klen = SPLITK > 1 ? (K / SPLITK) : K;

    float c[4][4][4] = {};
    uint32_t sbase = (uint32_t)__cvta_generic_to_shared(smem);
    int am = tid >> 2, aq = (tid & 3) * 8;

    auto load_stage = [&](int st, int k0) {
        uint32_t aoff = sbase + (uint32_t)st * STG * 2;
        #pragma unroll
        for (int i = 0; i < 2; i++) {
            int m = am + i * 64;
            size_t g = (size_t)(row0 + m) * K + k0 + aq;
            cpa16(aoff + (m * AST + aq) * 2, Ah + g);
            cpa16(aoff + (ASZ + m * AST + aq) * 2, Al + g);
        }
        uint32_t boff = aoff + 2 * ASZ * 2;
        if (!TRANSB) {
            #pragma unroll
            for (int i = 0; i < 2; i++) {
                int k = (tid >> 4) + i * 16, q = (tid & 15) * 8;
                size_t g = (size_t)(k0 + k) * N + col0 + q;   // N % 128 == 0 here
                cpa16(boff + (k * BST + q) * 2, Bh + g);
                cpa16(boff + (BSZ + k * BST + q) * 2, Bl + g);
            }
        } else {
            #pragma unroll
            for (int i = 0; i < 2; i++) {
                int n = (tid >> 2) + i * 64, q = (tid & 3) * 8;
                if (col0 + n < N) {
                    size_t g = (size_t)(col0 + n) * K + k0 + q;
                    cpa16(boff + (n * BST + q) * 2, Bh + g);
                    cpa16(boff + (BSZ + n * BST + q) * 2, Bl + g);
                }
            }
        }
    };

    int nit = klen / 32;
    load_stage(0, kbeg);          cpcommit();
    load_stage(1, kbeg + 32);     cpcommit();

    for (int it = 0; it < nit; it++) {
        int j = it + 2;
        if (j < nit)            { load_stage(j % NSTG, kbeg + j * 32); cpcommit(); cpwait<2>(); }
        else if (it + 1 < nit)  { cpwait<1>(); }
        else                    { cpwait<0>(); }
        __syncthreads();

        int cur = it % NSTG;
        uint32_t sA   = sbase + (uint32_t)cur * STG * 2;
        uint32_t sAl_ = sA + ASZ * 2;
        uint32_t sB   = sA + 2 * ASZ * 2;
        uint32_t sBl_ = sB + BSZ * 2;

        #pragma unroll
        for (int kk = 0; kk < 32; kk += 16) {
            uint32_t fah[4][4], fal[4][4], fbh[2][4], fbl[2][4];
            int abase = ((wm * 64 + (lane & 15)) * AST + (lane >> 4) * 8 + kk) * 2;
            #pragma unroll
            for (int mf = 0; mf < 4; mf++) {
                ldmx4(fah[mf], sA   + abase + mf * 16 * AST * 2);
                ldmx4(fal[mf], sAl_ + abase + mf * 16 * AST * 2);
            }
            if (!TRANSB) {
                int bbase = (((lane & 7) + ((lane >> 3) & 1) * 8 + kk) * BST
                             + wn * 32 + ((lane >> 4) & 1) * 8) * 2;
                ldmx4t(fbh[0], sB + bbase);   ldmx4t(fbh[1], sB + bbase + 32);
                ldmx4t(fbl[0], sBl_ + bbase); ldmx4t(fbl[1], sBl_ + bbase + 32);
            } else {
                int bbase = ((wn * 32 + (lane & 7) + ((lane >> 4) & 1) * 8) * BST
                             + ((lane >> 3) & 1) * 8 + kk) * 2;
                ldmx4(fbh[0], sB + bbase);   ldmx4(fbh[1], sB + bbase + 16 * BST * 2);
                ldmx4(fbl[0], sBl_ + bbase); ldmx4(fbl[1], sBl_ + bbase + 16 * BST * 2);
            }
            #pragma unroll
            for (int mf = 0; mf < 4; mf++)
                #pragma unroll
                for (int nf = 0; nf < 4; nf++) {
                    const uint32_t* bh2 = &fbh[nf >> 1][(nf & 1) * 2];
                    const uint32_t* bl2 = &fbl[nf >> 1][(nf & 1) * 2];
                    mma16816(c[mf][nf], fah[mf], bh2);
                    mma16816(c[mf][nf], fah[mf], bl2);
                    mma16816(c[mf][nf], fal[mf], bh2);
                }
        }
        __syncthreads();
    }

    int g = lane >> 2, t = lane & 3;
    #pragma unroll
    for (int mf = 0; mf < 4; mf++) {
        #pragma unroll
        for (int nf = 0; nf < 4; nf++) {
            int r  = row0 + wm * 64 + mf * 16 + g;
            int cc = col0 + wn * 32 + nf * 8 + t * 2;
            float* p0 = C + (size_t)r * N + cc;
            float* p1 = C + (size_t)(r + 8) * N + cc;
            if (SPLITK > 1) {
                if (cc < N)     { atomicAdd(p0,     c[mf][nf][0]); atomicAdd(p1,     c[mf][nf][2]); }
                if (cc + 1 < N) { atomicAdd(p0 + 1, c[mf][nf][1]); atomicAdd(p1 + 1, c[mf][nf][3]); }
            } else {
                if (cc < N) {
                    if (ACCUM) { p0[0] += c[mf][nf][0]; p1[0] += c[mf][nf][2]; }
                    else       { p0[0]  = c[mf][nf][0]; p1[0]  = c[mf][nf][2]; }
                }
                if (cc + 1 < N) {
                    if (ACCUM) { p0[1] += c[mf][nf][1]; p1[1] += c[mf][nf][3]; }
                    else       { p0[1]  = c[mf][nf][1]; p1[1]  = c[mf][nf][3]; }
                }
            }
        }
    }
}

// fused RoPE + bf16 hi/lo split of qkv (q pre-scaled by 1/8; v passthrough split)
__global__ void rope_split_kernel() {
    int row = blockIdx.x;
    int t = row % TT;
    int i = threadIdx.x;                  // 576 = 18 heads * 32
    int head = i >> 5, d = i & 31;
    size_t base;
    float a0, a1;
    if (head < HH + NKV) {
        float sc = head < HH ? 0.125f : 1.0f;
        int off = head < HH ? head * HS : DD + (head - HH) * HS;
        base = (size_t)row * QKV + off;
        float freq = powf(10000.f, (float)d / 32.0f);
        float s, c;
        sincosf((float)t / freq, &s, &c);
        float xr = g_qkv[base + d], xi = g_qkv[base + d + 32];
        a0 = (xr * c - xi * s) * sc;
        a1 = (xi * c + xr * s) * sc;
    } else {
        base = (size_t)row * QKV + DD + KVD + (head - HH - NKV) * HS;
        a0 = g_qkv[base + d];
        a1 = g_qkv[base + d + 32];
    }
    __nv_bfloat16 h0, l0, h1, l1;
    bf16_split(a0, h0, l0); bf16_split(a1, h1, l1);
    g_qkvh[base + d] = h0;      g_qkvl[base + d] = l0;
    g_qkvh[base + d + 32] = h1; g_qkvl[base + d + 32] = l1;
}

// flash attention, bf16x3 mma.sync, 128-query tiles
#define AT_ST 72
#define ATN_SMEM ((2 * 128 * AT_ST + 4 * 64 * AT_ST) * 2)
__global__ __launch_bounds__(256) void attn_mma() {
    extern __shared__ __nv_bfloat16 sm[];
    __nv_bfloat16* Qh = sm;
    __nv_bfloat16* Ql = Qh + 128 * AT_ST;
    __nv_bfloat16* Kh = Ql + 128 * AT_ST;
    __nv_bfloat16* Kl = Kh + 64 * AT_ST;
    __nv_bfloat16* Vh = Kl + 64 * AT_ST;
    __nv_bfloat16* Vl = Vh + 64 * AT_ST;
    int tid = threadIdx.x, lane = tid & 31, w = tid >> 5;
    int q0 = blockIdx.x * 128;
    int b = blockIdx.y / HH, h = blockIdx.y % HH, kvh = h % NKV;
    uint32_t sQh = (uint32_t)__cvta_generic_to_shared(Qh);
    uint32_t sQl = (uint32_t)__cvta_generic_to_shared(Ql);
    uint32_t sKh = (uint32_t)__cvta_generic_to_shared(Kh);
    uint32_t sKl = (uint32_t)__cvta_generic_to_shared(Kl);
    uint32_t sVh = (uint32_t)__cvta_generic_to_shared(Vh);
    uint32_t sVl = (uint32_t)__cvta_generic_to_shared(Vl);

    for (int i = tid; i < 128 * 8; i += 256) {
        int row = i >> 3, q8 = (i & 7) * 8;
        size_t g = (size_t)(b * TT + q0 + row) * QKV + h * HS + q8;
        *(uint4*)&Qh[row * AT_ST + q8] = *(const uint4*)&g_qkvh[g];
        *(uint4*)&Ql[row * AT_ST + q8] = *(const uint4*)&g_qkvl[g];
    }
    __syncthreads();
    uint32_t qfh[4][4], qfl[4][4];
    {
        int abase = ((w * 16 + (lane & 15)) * AT_ST + (lane >> 4) * 8) * 2;
        #pragma unroll
        for (int kp = 0; kp < 4; kp++) {
            ldmx4(qfh[kp], sQh + abase + kp * 32);
            ldmx4(qfl[kp], sQl + abase + kp * 32);
        }
    }
    float m0 = -1e30f, m1 = -1e30f, l0 = 0.f, l1 = 0.f;
    float co[8][4] = {};
    int r_seq = q0 + w * 16 + (lane >> 2);
    int nt = q0 / 64 + 2;

    for (int it = 0; it < nt; it++) {
        int s0 = it * 64;
        __syncthreads();
        for (int i = tid; i < 64 * 8; i += 256) {
            int row = i >> 3, q8 = (i & 7) * 8;
            size_t gk = (size_t)(b * TT + s0 + row) * QKV + DD + kvh * HS + q8;
            size_t gv = gk + KVD;
            *(uint4*)&Kh[row * AT_ST + q8] = *(const uint4*)&g_qkvh[gk];
            *(uint4*)&Kl[row * AT_ST + q8] = *(const uint4*)&g_qkvl[gk];
            *(uint4*)&Vh[row * AT_ST + q8] = *(const uint4*)&g_qkvh[gv];
            *(uint4*)&Vl[row * AT_ST + q8] = *(const uint4*)&g_qkvl[gv];
        }
        __syncthreads();
        float cs[8][4] = {};
        #pragma unroll
        for (int kp = 0; kp < 4; kp++) {
            #pragma unroll
            for (int ng = 0; ng < 4; ng++) {
                uint32_t bh[4], bl[4];
                int bbase = ((ng * 16 + (lane & 7) + ((lane >> 4) & 1) * 8) * AT_ST
                             + ((lane >> 3) & 1) * 8 + kp * 16) * 2;
                ldmx4(bh, sKh + bbase);
                ldmx4(bl, sKl + bbase);
                mma16816(cs[2 * ng],     qfh[kp], &bh[0]);
                mma16816(cs[2 * ng],     qfh[kp], &bl[0]);
                mma16816(cs[2 * ng],     qfl[kp], &bh[0]);
                mma16816(cs[2 * ng + 1], qfh[kp], &bh[2]);
                mma16816(cs[2 * ng + 1], qfh[kp], &bl[2]);
                mma16816(cs[2 * ng + 1], qfl[kp], &bh[2]);
            }
        }
        if (s0 + 63 > q0 + w * 16) {
            #pragma unroll
            for (int nf = 0; nf < 8; nf++) {
                int key = s0 + nf * 8 + (lane & 3) * 2;
                if (key     > r_seq)     cs[nf][0] = -1e30f;
                if (key + 1 > r_seq)     cs[nf][1] = -1e30f;
                if (key     > r_seq + 8) cs[nf][2] = -1e30f;
                if (key + 1 > r_seq + 8) cs[nf][3] = -1e30f;
            }
        }
        float mx0 = cs[0][0], mx1 = cs[0][2];
        #pragma unroll
        for (int nf = 0; nf < 8; nf++) {
            mx0 = fmaxf(mx0, fmaxf(cs[nf][0], cs[nf][1]));
            mx1 = fmaxf(mx1, fmaxf(cs[nf][2], cs[nf][3]));
        }
        mx0 = fmaxf(mx0, __shfl_xor_sync(0xffffffffu, mx0, 1));
        mx0 = fmaxf(mx0, __shfl_xor_sync(0xffffffffu, mx0, 2));
        mx1 = fmaxf(mx1, __shfl_xor_sync(0xffffffffu, mx1, 1));
        mx1 = fmaxf(mx1, __shfl_xor_sync(0xffffffffu, mx1, 2));
        float nm0 = fmaxf(m0, mx0), nm1 = fmaxf(m1, mx1);
        float corr0 = __expf(m0 - nm0), corr1 = __expf(m1 - nm1);
        m0 = nm0; m1 = nm1;
        uint32_t pfh[4][4], pfl[4][4];
        float sum0 = 0.f, sum1 = 0.f;
        #pragma unroll
        for (int nf = 0; nf < 8; nf++) {
            float p0 = __expf(cs[nf][0] - nm0), p1 = __expf(cs[nf][1] - nm0);
            float p2 = __expf(cs[nf][2] - nm1), p3 = __expf(cs[nf][3] - nm1);
            sum0 += p0 + p1; sum1 += p2 + p3;
            __nv_bfloat16 h0, lo0, h1, lo1, h2, lo2, h3, lo3;
            bf16_split(p0, h0, lo0); bf16_split(p1, h1, lo1);
            bf16_split(p2, h2, lo2); bf16_split(p3, h3, lo3);
            int kp = nf >> 1, o = (nf & 1) * 2;
            pfh[kp][o]     = packbf(h0, h1);   pfh[kp][o + 1] = packbf(h2, h3);
            pfl[kp][o]     = packbf(lo0, lo1); pfl[kp][o + 1] = packbf(lo2, lo3);
        }
        sum0 += __shfl_xor_sync(0xffffffffu, sum0, 1);
        sum0 += __shfl_xor_sync(0xffffffffu, sum0, 2);
        sum1 += __shfl_xor_sync(0xffffffffu, sum1, 1);
        sum1 += __shfl_xor_sync(0xffffffffu, sum1, 2);
        l0 = l0 * corr0 + sum0;
        l1 = l1 * corr1 + sum1;
        #pragma unroll
        for (int nf = 0; nf < 8; nf++) {
            co[nf][0] *= corr0; co[nf][1] *= corr0;
            co[nf][2] *= corr1; co[nf][3] *= corr1;
        }
        #pragma unroll
        for (int kp = 0; kp < 4; kp++) {
            #pragma unroll
            for (int ng = 0; ng < 4; ng++) {
                uint32_t bh[4], bl[4];
                int bbase = (((lane & 7) + ((lane >> 3) & 1) * 8 + kp * 16) * AT_ST
                             + ng * 16 + ((lane >> 4) & 1) * 8) * 2;
                ldmx4t(bh, sVh + bbase);
                ldmx4t(bl, sVl + bbase);
                mma16816(co[2 * ng],     pfh[kp], &bh[0]);
                mma16816(co[2 * ng],     pfh[kp], &bl[0]);
                mma16816(co[2 * ng],     pfl[kp], &bh[0]);
                mma16816(co[2 * ng + 1], pfh[kp], &bh[2]);
                mma16816(co[2 * ng + 1], pfh[kp], &bl[2]);
                mma16816(co[2 * ng + 1], pfl[kp], &bh[2]);
            }
        }
    }
    float il0 = 1.f / l0, il1 = 1.f / l1;
    size_t base0 = (size_t)(b * TT + r_seq) * DD + h * HS;
    size_t base1 = base0 + (size_t)8 * DD;
    #pragma unroll
    for (int nf = 0; nf < 8; nf++) {
        int cc = nf * 8 + (lane & 3) * 2;
        float y0 = co[nf][0] * il0, y1 = co[nf][1] * il0;
        float y2 = co[nf][2] * il1, y3 = co[nf][3] * il1;
        __nv_bfloat16 h0, lo0, h1, lo1, h2, lo2, h3, lo3;
        bf16_split(y0, h0, lo0); bf16_split(y1, h1, lo1);
        bf16_split(y2, h2, lo2); bf16_split(y3, h3, lo3);
        *(__nv_bfloat162*)&g_yh[base0 + cc] = __halves2bfloat162(h0, h1);
        *(__nv_bfloat162*)&g_yl[base0 + cc] = __halves2bfloat162(lo0, lo1);
        *(__nv_bfloat162*)&g_yh[base1 + cc] = __halves2bfloat162(h2, h3);
        *(__nv_bfloat162*)&g_yl[base1 + cc] = __halves2bfloat162(lo2, lo3);
    }
}

__global__ void silu_mul_kernel() {
    int i4 = blockIdx.x * 256 + threadIdx.x;
    int row = i4 >> 9, col = (i4 & 511) * 4;
    float4 gv = *(const float4*)&g_gu[(size_t)row * GU + col];
    float4 uv = *(const float4*)&g_gu[(size_t)row * GU + II + col];
    float r0 = gv.x / (1.f + __expf(-gv.x)) * uv.x;
    float r1 = gv.y / (1.f + __expf(-gv.y)) * uv.y;
    float r2 = gv.z / (1.f + __expf(-gv.z)) * uv.z;
    float r3 = gv.w / (1.f + __expf(-gv.w)) * uv.w;
    __nv_bfloat16 h0, l0, h1, l1, h2, l2, h3, l3;
    bf16_split(r0, h0, l0); bf16_split(r1, h1, l1);
    bf16_split(r2, h2, l2); bf16_split(r3, h3, l3);
    size_t o = (size_t)row * II + col;
    *(__nv_bfloat162*)&g_ah[o]     = __halves2bfloat162(h0, h1);
    *(__nv_bfloat162*)&g_ah[o + 2] = __halves2bfloat162(h2, h3);
    *(__nv_bfloat162*)&g_al[o]     = __halves2bfloat162(l0, l1);
    *(__nv_bfloat162*)&g_al[o + 2] = __halves2bfloat162(l2, l3);
}

static inline int sgrid(size_t n4) { return (int)((n4 + 255) / 256); }

extern "C" void kernel_launch(void* const* d_in, const int* in_sizes, int n_in,
                              void* d_out, int out_size) {
    const int*   idx   = (const int*)d_in[0];
    const float* embed = (const float*)d_in[1];
    const float* ln1   = (const float*)d_in[2];
    const float* qw    = (const float*)d_in[3];
    const float* kw    = (const float*)d_in[4];
    const float* vw    = (const float*)d_in[5];
    const float* ow    = (const float*)d_in[6];
    const float* ln2   = (const float*)d_in[7];
    const float* gw    = (const float*)d_in[8];
    const float* uw    = (const float*)d_in[9];
    const float* dw    = (const float*)d_in[10];
    const float* nw    = (const float*)d_in[11];
    float* out = (float*)d_out;

    float *px, *pqkv, *pgu;
    cudaGetSymbolAddress((void**)&px,   g_x);
    cudaGetSymbolAddress((void**)&pqkv, g_qkv);
    cudaGetSymbolAddress((void**)&pgu,  g_gu);
    __nv_bfloat16 *hh, *hl, *yh, *yl, *ah, *al;
    cudaGetSymbolAddress((void**)&hh, g_hh); cudaGetSymbolAddress((void**)&hl, g_hl);
    cudaGetSymbolAddress((void**)&yh, g_yh); cudaGetSymbolAddress((void**)&yl, g_yl);
    cudaGetSymbolAddress((void**)&ah, g_ah); cudaGetSymbolAddress((void**)&al, g_al);
    __nv_bfloat16 *qkvwh, *qkvwl, *owh, *owl, *guwh, *guwl, *dwh, *dwl, *emh, *eml;
    cudaGetSymbolAddress((void**)&qkvwh, s_qkvw_h); cudaGetSymbolAddress((void**)&qkvwl, s_qkvw_l);
    cudaGetSymbolAddress((void**)&owh, s_ow_h);     cudaGetSymbolAddress((void**)&owl, s_ow_l);
    cudaGetSymbolAddress((void**)&guwh, s_guw_h);   cudaGetSymbolAddress((void**)&guwl, s_guw_l);
    cudaGetSymbolAddress((void**)&dwh, s_dw_h);     cudaGetSymbolAddress((void**)&dwl, s_dw_l);
    cudaGetSymbolAddress((void**)&emh, s_em_h);     cudaGetSymbolAddress((void**)&eml, s_em_l);

    // 3-stage dynamic smem sizes
    const int SM_G0 = 3 * (2 * (128 * 40) + 2 * (32 * 136)) * 2;   // 113664 B
    const int SM_G1 = 3 * (2 * (128 * 40) + 2 * (128 * 40)) * 2;   // 122880 B
    cudaFuncSetAttribute(bgemm<0, 0, 1, 0>, cudaFuncAttributeMaxDynamicSharedMemorySize, SM_G0);
    cudaFuncSetAttribute(bgemm<0, 1, 2, 0>, cudaFuncAttributeMaxDynamicSharedMemorySize, SM_G0);
    cudaFuncSetAttribute(bgemm<1, 0, 1, 1>, cudaFuncAttributeMaxDynamicSharedMemorySize, SM_G1);
    cudaFuncSetAttribute(attn_mma, cudaFuncAttributeMaxDynamicSharedMemorySize, ATN_SMEM);

    // prologue: pack/split weights
    pack_qkv4<<<NL * DD * 288 / 256, 256>>>(qw, kw, vw);
    pack_gu4 <<<NL * DD * 1024 / 256, 256>>>(gw, uw);
    split_kernel<<<sgrid((size_t)NL * DD * DD / 4), 256>>>(ow, owh, owl, NL * DD * DD / 4);
    split_kernel<<<sgrid((size_t)NL * II * DD / 4), 256>>>(dw, dwh, dwl, NL * II * DD / 4);
    split_kernel<<<sgrid((size_t)VV * DD / 4), 256>>>(embed, emh, eml, VV * DD / 4);

    dim3 gqkv(QKV / 128, BT / 128);           // (9,16)
    dim3 go(DD / 128, BT / 128, 2);           // (6,16,2) split-K
    dim3 ggu(GU / 128, BT / 128);             // (32,16)
    dim3 ga(TT / 128, 2 * HH);                // (8,24)
    dim3 gl(BT / 128, (VV + 127) / 128);      // MSWAP: x=m(16), y=n(393)

    embed_kernel<<<BT, 192>>>(idx, embed);

    for (int l = 0; l < NL; l++) {
        size_t oQ  = (size_t)l * DD * QKV;
        size_t oO  = (size_t)l * DD * DD;
        size_t oG  = (size_t)l * DD * GU;
        size_t oD2 = (size_t)l * II * DD;
        rmsnorm_split<<<BT, 256>>>(px, ln1 + (size_t)l * DD, hh, hl);
        bgemm<0, 0, 1, 0><<<gqkv, 256, SM_G0>>>(hh, hl, qkvwh + oQ, qkvwl + oQ, pqkv, BT, QKV, DD);
        rope_split_kernel<<<BT, 576>>>();
        attn_mma<<<ga, 256, ATN_SMEM>>>();
        bgemm<0, 1, 2, 0><<<go, 256, SM_G0>>>(yh, yl, owh + oO, owl + oO, px, BT, DD, DD);
        rmsnorm_split<<<BT, 256>>>(px, ln2 + (size_t)l * DD, hh, hl);
        bgemm<0, 0, 1, 0><<<ggu, 256, SM_G0>>>(hh, hl, guwh + oG, guwl + oG, pgu, BT, GU, DD);
        silu_mul_kernel<<<BT * II / 4 / 256, 256>>>();
        bgemm<0, 1, 2, 0><<<go, 256, SM_G0>>>(ah, al, dwh + oD2, dwl + oD2, px, BT, DD, II);
    }
    rmsnorm_split<<<BT, 256>>>(px, nw, hh, hl);
    bgemm<1, 0, 1, 1><<<gl, 256, SM_G1>>>(hh, hl, emh, eml, out, BT, VV, DD);
}

// round 11
// speedup vs baseline: 1.1234x; 1.1233x over previous
#include <cuda_runtime.h>
#include <cuda_bf16.h>
#include <cuda_fp16.h>
#include <math.h>
#include <stdint.h>

#define BT   2048
#define TT   1024
#define DD   768
#define HH   12
#define HS   64
#define NKV  3
#define NL   12
#define II   2048
#define VV   50257
#define KVD  192
#define QKV  1152
#define GU   4096
#define EPS_ 1e-6f

// fp32 scratch
__device__ float g_x[BT * DD];
__device__ float g_qkv[BT * QKV];
// bf16 split activations
__device__ __nv_bfloat16 g_hh[BT * DD],  g_hl[BT * DD];
__device__ __nv_bfloat16 g_qkvh[BT * QKV], g_qkvl[BT * QKV];
__device__ __nv_bfloat16 g_yh[BT * DD],  g_yl[BT * DD];
__device__ __nv_bfloat16 g_ah[BT * II],  g_al[BT * II];
// fp16 activation for LM head
__device__ __half g_fh[BT * DD];
// bf16 split weights ([K][N] layout); gu interleaved (2j=gate_j, 2j+1=up_j)
__device__ __nv_bfloat16 s_qkvw_h[NL * DD * QKV], s_qkvw_l[NL * DD * QKV];
__device__ __nv_bfloat16 s_ow_h[NL * DD * DD],    s_ow_l[NL * DD * DD];
__device__ __nv_bfloat16 s_guw_h[NL * DD * GU],   s_guw_l[NL * DD * GU];
__device__ __nv_bfloat16 s_dw_h[NL * II * DD],    s_dw_l[NL * II * DD];
// fp16 split embed (scaled x1024), [V][K]
__device__ __half s_em_h[(size_t)VV * DD], s_em_l[(size_t)VV * DD];

__device__ __forceinline__ void bf16_split(float v, __nv_bfloat16& h, __nv_bfloat16& l) {
    h = __float2bfloat16(v);
    l = __float2bfloat16(v - __bfloat162float(h));
}
__device__ __forceinline__ uint32_t packbf(__nv_bfloat16 a, __nv_bfloat16 b) {
    __nv_bfloat162 t = __halves2bfloat162(a, b);
    return *(uint32_t*)&t;
}
__device__ __forceinline__ void ldmx4(uint32_t* r, uint32_t a) {
    asm volatile("ldmatrix.sync.aligned.m8n8.x4.shared.b16 {%0,%1,%2,%3}, [%4];"
                 : "=r"(r[0]), "=r"(r[1]), "=r"(r[2]), "=r"(r[3]) : "r"(a));
}
__device__ __forceinline__ void ldmx4t(uint32_t* r, uint32_t a) {
    asm volatile("ldmatrix.sync.aligned.m8n8.x4.trans.shared.b16 {%0,%1,%2,%3}, [%4];"
                 : "=r"(r[0]), "=r"(r[1]), "=r"(r[2]), "=r"(r[3]) : "r"(a));
}
__device__ __forceinline__ void mma16816(float* c, const uint32_t* a, const uint32_t* b) {
    asm volatile("mma.sync.aligned.m16n8k16.row.col.f32.bf16.bf16.f32 "
                 "{%0,%1,%2,%3}, {%4,%5,%6,%7}, {%8,%9}, {%0,%1,%2,%3};"
                 : "+f"(c[0]), "+f"(c[1]), "+f"(c[2]), "+f"(c[3])
                 : "r"(a[0]), "r"(a[1]), "r"(a[2]), "r"(a[3]), "r"(b[0]), "r"(b[1]));
}
__device__ __forceinline__ void mma16816h(float* c, const uint32_t* a, const uint32_t* b) {
    asm volatile("mma.sync.aligned.m16n8k16.row.col.f32.f16.f16.f32 "
                 "{%0,%1,%2,%3}, {%4,%5,%6,%7}, {%8,%9}, {%0,%1,%2,%3};"
                 : "+f"(c[0]), "+f"(c[1]), "+f"(c[2]), "+f"(c[3])
                 : "r"(a[0]), "r"(a[1]), "r"(a[2]), "r"(a[3]), "r"(b[0]), "r"(b[1]));
}
__device__ __forceinline__ void cpa16(uint32_t dst, const void* src) {
    asm volatile("cp.async.cg.shared.global [%0], [%1], 16;" :: "r"(dst), "l"(src));
}
__device__ __forceinline__ void cpcommit() { asm volatile("cp.async.commit_group;"); }
template<int N> __device__ __forceinline__ void cpwait() {
    asm volatile("cp.async.wait_group %0;" :: "n"(N));
}

// fp32 -> bf16 hi/lo splitter
__global__ void split_kernel(const float* __restrict__ s, __nv_bfloat16* __restrict__ h,
                             __nv_bfloat16* __restrict__ l, int n4) {
    int i = blockIdx.x * 256 + threadIdx.x;
    if (i >= n4) return;
    float4 v = ((const float4*)s)[i];
    __nv_bfloat16 h0, h1, h2, h3, l0, l1, l2, l3;
    bf16_split(v.x, h0, l0); bf16_split(v.y, h1, l1);
    bf16_split(v.z, h2, l2); bf16_split(v.w, h3, l3);
    __nv_bfloat162* hp = (__nv_bfloat162*)(h + (size_t)i * 4);
    __nv_bfloat162* lp = (__nv_bfloat162*)(l + (size_t)i * 4);
    hp[0] = __halves2bfloat162(h0, h1); hp[1] = __halves2bfloat162(h2, h3);
    lp[0] = __halves2bfloat162(l0, l1); lp[1] = __halves2bfloat162(l2, l3);
}

// fp32 -> fp16 hi/lo splitter with x1024 scale (embed for fp16 LM head)
__global__ void split_kernel_h(const float* __restrict__ s, __half* __restrict__ h,
                               __half* __restrict__ l, int n4) {
    int i = blockIdx.x * 256 + threadIdx.x;
    if (i >= n4) return;
    float4 v = ((const float4*)s)[i];
    float x0 = v.x * 1024.f, x1 = v.y * 1024.f, x2 = v.z * 1024.f, x3 = v.w * 1024.f;
    __half h0 = __float2half(x0), h1 = __float2half(x1);
    __half h2 = __float2half(x2), h3 = __float2half(x3);
    __half l0 = __float2half(x0 - __half2float(h0));
    __half l1 = __float2half(x1 - __half2float(h1));
    __half l2 = __float2half(x2 - __half2float(h2));
    __half l3 = __float2half(x3 - __half2float(h3));
    __half2* hp = (__half2*)(h + (size_t)i * 4);
    __half2* lp = (__half2*)(l + (size_t)i * 4);
    hp[0] = __halves2half2(h0, h1); hp[1] = __halves2half2(h2, h3);
    lp[0] = __halves2half2(l0, l1); lp[1] = __halves2half2(l2, l3);
}

// pack qkv weights -> [D][1152]
__global__ void pack_qkv4(const float* __restrict__ qw, const float* __restrict__ kw,
                          const float* __restrict__ vw) {
    int i4 = blockIdx.x * 256 + threadIdx.x;
    int c4 = (i4 % 288) * 4;
    int rl = i4 / 288;
    int row = rl % DD, l = rl / DD;
    const float* src;
    if (c4 < DD)            src = qw + ((size_t)l * DD + row) * DD + c4;
    else if (c4 < DD + KVD) src = kw + ((size_t)l * DD + row) * KVD + (c4 - DD);
    else                    src = vw + ((size_t)l * DD + row) * KVD + (c4 - DD - KVD);
    float4 v = *(const float4*)src;
    __nv_bfloat16 h0, h1, h2, h3, l0, l1, l2, l3;
    bf16_split(v.x, h0, l0); bf16_split(v.y, h1, l1);
    bf16_split(v.z, h2, l2); bf16_split(v.w, h3, l3);
    __nv_bfloat162* hp = (__nv_bfloat162*)(s_qkvw_h + (size_t)i4 * 4);
    __nv_bfloat162* lp = (__nv_bfloat162*)(s_qkvw_l + (size_t)i4 * 4);
    hp[0] = __halves2bfloat162(h0, h1); hp[1] = __halves2bfloat162(h2, h3);
    lp[0] = __halves2bfloat162(l0, l1); lp[1] = __halves2bfloat162(l2, l3);
}

// pack gate/up weights INTERLEAVED -> [D][4096]: col 2j = gate_j, col 2j+1 = up_j
__global__ void pack_gu4(const float* __restrict__ gw, const float* __restrict__ uw) {
    int i4 = blockIdx.x * 256 + threadIdx.x;
    int c4 = (i4 & 1023) * 4;
    int rl = i4 >> 10;
    int row = rl % DD, l = rl / DD;
    int j = c4 >> 1;
    float2 gv = *(const float2*)(gw + ((size_t)l * DD + row) * II + j);
    float2 uv = *(const float2*)(uw + ((size_t)l * DD + row) * II + j);
    float4 v = make_float4(gv.x, uv.x, gv.y, uv.y);
    __nv_bfloat16 h0, h1, h2, h3, l0, l1, l2, l3;
    bf16_split(v.x, h0, l0); bf16_split(v.y, h1, l1);
    bf16_split(v.z, h2, l2); bf16_split(v.w, h3, l3);
    __nv_bfloat162* hp = (__nv_bfloat162*)(s_guw_h + (size_t)i4 * 4);
    __nv_bfloat162* lp = (__nv_bfloat162*)(s_guw_l + (size_t)i4 * 4);
    hp[0] = __halves2bfloat162(h0, h1); hp[1] = __halves2bfloat162(h2, h3);
    lp[0] = __halves2bfloat162(l0, l1); lp[1] = __halves2bfloat162(l2, l3);
}

__global__ void embed_kernel(const int* __restrict__ idx, const float* __restrict__ embed) {
    int row = blockIdx.x;
    const float4* src = (const float4*)(embed + (size_t)idx[row] * DD);
    ((float4*)(g_x + (size_t)row * DD))[threadIdx.x] = src[threadIdx.x];
}

__global__ __launch_bounds__(256) void rmsnorm_split(const float* __restrict__ in,
                                                     const float* __restrict__ w,
                                                     __nv_bfloat16* __restrict__ oh,
                                                     __nv_bfloat16* __restrict__ ol) {
    int row = blockIdx.x;
    const float* x = in + (size_t)row * DD;
    float s = 0.f;
    for (int i = threadIdx.x; i < DD; i += 256) { float v = x[i]; s += v * v; }
    #pragma unroll
    for (int o = 16; o; o >>= 1) s += __shfl_xor_sync(0xffffffffu, s, o);
    __shared__ float red[8];
    if ((threadIdx.x & 31) == 0) red[threadIdx.x >> 5] = s;
    __syncthreads();
    if (threadIdx.x < 8) {
        s = red[threadIdx.x];
        #pragma unroll
        for (int o = 4; o; o >>= 1) s += __shfl_xor_sync(0xffu, s, o);
        if (threadIdx.x == 0) red[0] = s;
    }
    __syncthreads();
    float inv = rsqrtf(red[0] / (float)DD + EPS_);
    for (int i = threadIdx.x; i < DD; i += 256) {
        float r = w[i] * x[i] * inv;
        __nv_bfloat16 h, l;
        bf16_split(r, h, l);
        oh[(size_t)row * DD + i] = h;
        ol[(size_t)row * DD + i] = l;
    }
}

// final rmsnorm -> single fp16 (for fp16 LM head)
__global__ __launch_bounds__(256) void rmsnorm_f16(const float* __restrict__ in,
                                                   const float* __restrict__ w) {
    int row = blockIdx.x;
    const float* x = in + (size_t)row * DD;
    float s = 0.f;
    for (int i = threadIdx.x; i < DD; i += 256) { float v = x[i]; s += v * v; }
    #pragma unroll
    for (int o = 16; o; o >>= 1) s += __shfl_xor_sync(0xffffffffu, s, o);
    __shared__ float red[8];
    if ((threadIdx.x & 31) == 0) red[threadIdx.x >> 5] = s;
    __syncthreads();
    if (threadIdx.x < 8) {
        s = red[threadIdx.x];
        #pragma unroll
        for (int o = 4; o; o >>= 1) s += __shfl_xor_sync(0xffu, s, o);
        if (threadIdx.x == 0) red[0] = s;
    }
    __syncthreads();
    float inv = rsqrtf(red[0] / (float)DD + EPS_);
    for (int i = threadIdx.x; i < DD; i += 256)
        g_fh[(size_t)row * DD + i] = __float2half(w[i] * x[i] * inv);
}

// ---------------- mma.sync GEMM, 2-stage cp.async pipeline ----------------
// C[M,N] = A[M,K] @ B (+C if ACCUM). TRANSB==0: B[K,N]; TRANSB==1: B[N,K].
// SPLITK: blockIdx.z K-range + atomicAdd epilogue. MSWAP: m from blockIdx.x.
// F16: fp16 2-term (Ah*Bh + Ah*Bl), output scaled by 1/1024 (embed pre-scaled).
// SILU: interleaved gate/up epilogue -> silu(g)*u -> g_ah/g_al bf16 split.
template<int TRANSB, int ACCUM, int SPLITK, int MSWAP, int F16, int SILU>
__global__ __launch_bounds__(256) void bgemm(const __nv_bfloat16* __restrict__ Ah,
                                             const __nv_bfloat16* __restrict__ Al,
                                             const __nv_bfloat16* __restrict__ Bh,
                                             const __nv_bfloat16* __restrict__ Bl,
                                             float* __restrict__ C,
                                             int M, int N, int K) {
    constexpr int AST   = 40;
    constexpr int BROWS = TRANSB ? 128 : 32;
    constexpr int BST   = TRANSB ? 40  : 136;
    constexpr int ASZ   = 128 * AST;
    constexpr int BSZ   = BROWS * BST;
    constexpr int STG   = 2 * ASZ + 2 * BSZ;

    extern __shared__ __nv_bfloat16 smem[];
    int tid  = threadIdx.x;
    int lane = tid & 31, wid = tid >> 5;
    int wm = wid >> 2, wn = wid & 3;
    int row0 = (MSWAP ? blockIdx.x : blockIdx.y) * 128;
    int col0 = (MSWAP ? blockIdx.y : blockIdx.x) * 128;
    int kbeg = SPLITK > 1 ? blockIdx.z * (K / SPLITK) : 0;
    int klen = SPLITK > 1 ? (K / SPLITK) : K;

    float c[4][4][4] = {};
    uint32_t sbase = (uint32_t)__cvta_generic_to_shared(smem);
    int am = tid >> 2, aq = (tid & 3) * 8;

    auto load_stage = [&](int st, int k0) {
        uint32_t aoff = sbase + (uint32_t)st * STG * 2;
        #pragma unroll
        for (int i = 0; i < 2; i++) {
            int m = am + i * 64;
            size_t g = (size_t)(row0 + m) * K + k0 + aq;
            cpa16(aoff + (m * AST + aq) * 2, Ah + g);
            if (!F16) cpa16(aoff + (ASZ + m * AST + aq) * 2, Al + g);
        }
        uint32_t boff = aoff + 2 * ASZ * 2;
        if (!TRANSB) {
            #pragma unroll
            for (int i = 0; i < 2; i++) {
                int k = (tid >> 4) + i * 16, q = (tid & 15) * 8;
                size_t g = (size_t)(k0 + k) * N + col0 + q;   // N % 128 == 0 here
                cpa16(boff + (k * BST + q) * 2, Bh + g);
                cpa16(boff + (BSZ + k * BST + q) * 2, Bl + g);
            }
        } else {
            #pragma unroll
            for (int i = 0; i < 2; i++) {
                int n = (tid >> 2) + i * 64, q = (tid & 3) * 8;
                if (col0 + n < N) {
                    size_t g = (size_t)(col0 + n) * K + k0 + q;
                    cpa16(boff + (n * BST + q) * 2, Bh + g);
                    cpa16(boff + (BSZ + n * BST + q) * 2, Bl + g);
                }
            }
        }
    };

    int nit = klen / 32;
    load_stage(0, kbeg);
    cpcommit();

    for (int it = 0; it < nit; it++) {
        if (it + 1 < nit) { load_stage((it + 1) & 1, kbeg + (it + 1) * 32); cpcommit(); cpwait<1>(); }
        else              { cpwait<0>(); }
        __syncthreads();

        int cur = it & 1;
        uint32_t sA   = sbase + (uint32_t)cur * STG * 2;
        uint32_t sAl_ = sA + ASZ * 2;
        uint32_t sB   = sA + 2 * ASZ * 2;
        uint32_t sBl_ = sB + BSZ * 2;

        #pragma unroll
        for (int kk = 0; kk < 32; kk += 16) {
            uint32_t fah[4][4], fal[4][4], fbh[2][4], fbl[2][4];
            int abase = ((wm * 64 + (lane & 15)) * AST + (lane >> 4) * 8 + kk) * 2;
            #pragma unroll
            for (int mf = 0; mf < 4; mf++) {
                ldmx4(fah[mf], sA + abase + mf * 16 * AST * 2);
                if (!F16) ldmx4(fal[mf], sAl_ + abase + mf * 16 * AST * 2);
            }
            if (!TRANSB) {
                int bbase = (((lane & 7) + ((lane >> 3) & 1) * 8 + kk) * BST
                             + wn * 32 + ((lane >> 4) & 1) * 8) * 2;
                ldmx4t(fbh[0], sB + bbase);   ldmx4t(fbh[1], sB + bbase + 32);
                ldmx4t(fbl[0], sBl_ + bbase); ldmx4t(fbl[1], sBl_ + bbase + 32);
            } else {
                int bbase = ((wn * 32 + (lane & 7) + ((lane >> 4) & 1) * 8) * BST
                             + ((lane >> 3) & 1) * 8 + kk) * 2;
                ldmx4(fbh[0], sB + bbase);   ldmx4(fbh[1], sB + bbase + 16 * BST * 2);
                ldmx4(fbl[0], sBl_ + bbase); ldmx4(fbl[1], sBl_ + bbase + 16 * BST * 2);
            }
            #pragma unroll
            for (int mf = 0; mf < 4; mf++)
                #pragma unroll
                for (int nf = 0; nf < 4; nf++) {
                    const uint32_t* bh2 = &fbh[nf >> 1][(nf & 1) * 2];
                    const uint32_t* bl2 = &fbl[nf >> 1][(nf & 1) * 2];
                    if (F16) {
                        mma16816h(c[mf][nf], fah[mf], bh2);
                        mma16816h(c[mf][nf], fah[mf], bl2);
                    } else {
                        mma16816(c[mf][nf], fah[mf], bh2);
                        mma16816(c[mf][nf], fah[mf], bl2);
                        mma16816(c[mf][nf], fal[mf], bh2);
                    }
                }
        }
        __syncthreads();
    }

    const float osc = F16 ? (1.f / 1024.f) : 1.f;
    int g = lane >> 2, t = lane & 3;
    #pragma unroll
    for (int mf = 0; mf < 4; mf++) {
        #pragma unroll
        for (int nf = 0; nf < 4; nf++) {
            int r  = row0 + wm * 64 + mf * 16 + g;
            int cc = col0 + wn * 32 + nf * 8 + t * 2;
            if (SILU) {
                int j = cc >> 1;                       // cc always even
                float g0 = c[mf][nf][0], u0 = c[mf][nf][1];
                float g1 = c[mf][nf][2], u1 = c[mf][nf][3];
                float r0 = g0 / (1.f + __expf(-g0)) * u0;
                float r1 = g1 / (1.f + __expf(-g1)) * u1;
                __nv_bfloat16 h0, lo0, h1, lo1;
                bf16_split(r0, h0, lo0); bf16_split(r1, h1, lo1);
                g_ah[(size_t)r * II + j] = h0;
                g_al[(size_t)r * II + j] = lo0;
                g_ah[(size_t)(r + 8) * II + j] = h1;
                g_al[(size_t)(r + 8) * II + j] = lo1;
            } else {
                float* p0 = C + (size_t)r * N + cc;
                float* p1 = C + (size_t)(r + 8) * N + cc;
                if (SPLITK > 1) {
                    if (cc < N)     { atomicAdd(p0,     c[mf][nf][0]); atomicAdd(p1,     c[mf][nf][2]); }
                    if (cc + 1 < N) { atomicAdd(p0 + 1, c[mf][nf][1]); atomicAdd(p1 + 1, c[mf][nf][3]); }
                } else {
                    if (cc < N) {
                        if (ACCUM) { p0[0] += c[mf][nf][0]; p1[0] += c[mf][nf][2]; }
                        else       { p0[0] = c[mf][nf][0] * osc; p1[0] = c[mf][nf][2] * osc; }
                    }
                    if (cc + 1 < N) {
                        if (ACCUM) { p0[1] += c[mf][nf][1]; p1[1] += c[mf][nf][3]; }
                        else       { p0[1] = c[mf][nf][1] * osc; p1[1] = c[mf][nf][3] * osc; }
                    }
                }
            }
        }
    }
}

// fused RoPE + bf16 hi/lo split of qkv (q pre-scaled by 1/8; v passthrough split)
__global__ void rope_split_kernel() {
    int row = blockIdx.x;
    int t = row % TT;
    int i = threadIdx.x;                  // 576 = 18 heads * 32
    int head = i >> 5, d = i & 31;
    size_t base;
    float a0, a1;
    if (head < HH + NKV) {
        float sc = head < HH ? 0.125f : 1.0f;
        int off = head < HH ? head * HS : DD + (head - HH) * HS;
        base = (size_t)row * QKV + off;
        float freq = powf(10000.f, (float)d / 32.0f);
        float s, c;
        sincosf((float)t / freq, &s, &c);
        float xr = g_qkv[base + d], xi = g_qkv[base + d + 32];
        a0 = (xr * c - xi * s) * sc;
        a1 = (xi * c + xr * s) * sc;
    } else {
        base = (size_t)row * QKV + DD + KVD + (head - HH - NKV) * HS;
        a0 = g_qkv[base + d];
        a1 = g_qkv[base + d + 32];
    }
    __nv_bfloat16 h0, l0, h1, l1;
    bf16_split(a0, h0, l0); bf16_split(a1, h1, l1);
    g_qkvh[base + d] = h0;      g_qkvl[base + d] = l0;
    g_qkvh[base + d + 32] = h1; g_qkvl[base + d + 32] = l1;
}

// flash attention, bf16x3 mma.sync, 128-query tiles
#define AT_ST 72
#define ATN_SMEM ((2 * 128 * AT_ST + 4 * 64 * AT_ST) * 2)
__global__ __launch_bounds__(256) void attn_mma() {
    extern __shared__ __nv_bfloat16 sm[];
    __nv_bfloat16* Qh = sm;
    __nv_bfloat16* Ql = Qh + 128 * AT_ST;
    __nv_bfloat16* Kh = Ql + 128 * AT_ST;
    __nv_bfloat16* Kl = Kh + 64 * AT_ST;
    __nv_bfloat16* Vh = Kl + 64 * AT_ST;
    __nv_bfloat16* Vl = Vh + 64 * AT_ST;
    int tid = threadIdx.x, lane = tid & 31, w = tid >> 5;
    int q0 = blockIdx.x * 128;
    int b = blockIdx.y / HH, h = blockIdx.y % HH, kvh = h % NKV;
    uint32_t sQh = (uint32_t)__cvta_generic_to_shared(Qh);
    uint32_t sQl = (uint32_t)__cvta_generic_to_shared(Ql);
    uint32_t sKh = (uint32_t)__cvta_generic_to_shared(Kh);
    uint32_t sKl = (uint32_t)__cvta_generic_to_shared(Kl);
    uint32_t sVh = (uint32_t)__cvta_generic_to_shared(Vh);
    uint32_t sVl = (uint32_t)__cvta_generic_to_shared(Vl);

    for (int i = tid; i < 128 * 8; i += 256) {
        int row = i >> 3, q8 = (i & 7) * 8;
        size_t g = (size_t)(b * TT + q0 + row) * QKV + h * HS + q8;
        *(uint4*)&Qh[row * AT_ST + q8] = *(const uint4*)&g_qkvh[g];
        *(uint4*)&Ql[row * AT_ST + q8] = *(const uint4*)&g_qkvl[g];
    }
    __syncthreads();
    uint32_t qfh[4][4], qfl[4][4];
    {
        int abase = ((w * 16 + (lane & 15)) * AT_ST + (lane >> 4) * 8) * 2;
        #pragma unroll
        for (int kp = 0; kp < 4; kp++) {
            ldmx4(qfh[kp], sQh + abase + kp * 32);
            ldmx4(qfl[kp], sQl + abase + kp * 32);
        }
    }
    float m0 = -1e30f, m1 = -1e30f, l0 = 0.f, l1 = 0.f;
    float co[8][4] = {};
    int r_seq = q0 + w * 16 + (lane >> 2);
    int nt = q0 / 64 + 2;

    for (int it = 0; it < nt; it++) {
        int s0 = it * 64;
        __syncthreads();
        for (int i = tid; i < 64 * 8; i += 256) {
            int row = i >> 3, q8 = (i & 7) * 8;
            size_t gk = (size_t)(b * TT + s0 + row) * QKV + DD + kvh * HS + q8;
            size_t gv = gk + KVD;
            *(uint4*)&Kh[row * AT_ST + q8] = *(const uint4*)&g_qkvh[gk];
            *(uint4*)&Kl[row * AT_ST + q8] = *(const uint4*)&g_qkvl[gk];
            *(uint4*)&Vh[row * AT_ST + q8] = *(const uint4*)&g_qkvh[gv];
            *(uint4*)&Vl[row * AT_ST + q8] = *(const uint4*)&g_qkvl[gv];
        }
        __syncthreads();
        float cs[8][4] = {};
        #pragma unroll
        for (int kp = 0; kp < 4; kp++) {
            #pragma unroll
            for (int ng = 0; ng < 4; ng++) {
                uint32_t bh[4], bl[4];
                int bbase = ((ng * 16 + (lane & 7) + ((lane >> 4) & 1) * 8) * AT_ST
                             + ((lane >> 3) & 1) * 8 + kp * 16) * 2;
                ldmx4(bh, sKh + bbase);
                ldmx4(bl, sKl + bbase);
                mma16816(cs[2 * ng],     qfh[kp], &bh[0]);
                mma16816(cs[2 * ng],     qfh[kp], &bl[0]);
                mma16816(cs[2 * ng],     qfl[kp], &bh[0]);
                mma16816(cs[2 * ng + 1], qfh[kp], &bh[2]);
                mma16816(cs[2 * ng + 1], qfh[kp], &bl[2]);
                mma16816(cs[2 * ng + 1], qfl[kp], &bh[2]);
            }
        }
        if (s0 + 63 > q0 + w * 16) {
            #pragma unroll
            for (int nf = 0; nf < 8; nf++) {
                int key = s0 + nf * 8 + (lane & 3) * 2;
                if (key     > r_seq)     cs[nf][0] = -1e30f;
                if (key + 1 > r_seq)     cs[nf][1] = -1e30f;
                if (key     > r_seq + 8) cs[nf][2] = -1e30f;
                if (key + 1 > r_seq + 8) cs[nf][3] = -1e30f;
            }
        }
        float mx0 = cs[0][0], mx1 = cs[0][2];
        #pragma unroll
        for (int nf = 0; nf < 8; nf++) {
            mx0 = fmaxf(mx0, fmaxf(cs[nf][0], cs[nf][1]));
            mx1 = fmaxf(mx1, fmaxf(cs[nf][2], cs[nf][3]));
        }
        mx0 = fmaxf(mx0, __shfl_xor_sync(0xffffffffu, mx0, 1));
        mx0 = fmaxf(mx0, __shfl_xor_sync(0xffffffffu, mx0, 2));
        mx1 = fmaxf(mx1, __shfl_xor_sync(0xffffffffu, mx1, 1));
        mx1 = fmaxf(mx1, __shfl_xor_sync(0xffffffffu, mx1, 2));
        float nm0 = fmaxf(m0, mx0), nm1 = fmaxf(m1, mx1);
        float corr0 = __expf(m0 - nm0), corr1 = __expf(m1 - nm1);
        m0 = nm0; m1 = nm1;
        uint32_t pfh[4][4], pfl[4][4];
        float sum0 = 0.f, sum1 = 0.f;
        #pragma unroll
        for (int nf = 0; nf < 8; nf++) {
            float p0 = __expf(cs[nf][0] - nm0), p1 = __expf(cs[nf][1] - nm0);
            float p2 = __expf(cs[nf][2] - nm1), p3 = __expf(cs[nf][3] - nm1);
            sum0 += p0 + p1; sum1 += p2 + p3;
            __nv_bfloat16 h0, lo0, h1, lo1, h2, lo2, h3, lo3;
            bf16_split(p0, h0, lo0); bf16_split(p1, h1, lo1);
            bf16_split(p2, h2, lo2); bf16_split(p3, h3, lo3);
            int kp = nf >> 1, o = (nf & 1) * 2;
            pfh[kp][o]     = packbf(h0, h1);   pfh[kp][o + 1] = packbf(h2, h3);
            pfl[kp][o]     = packbf(lo0, lo1); pfl[kp][o + 1] = packbf(lo2, lo3);
        }
        sum0 += __shfl_xor_sync(0xffffffffu, sum0, 1);
        sum0 += __shfl_xor_sync(0xffffffffu, sum0, 2);
        sum1 += __shfl_xor_sync(0xffffffffu, sum1, 1);
        sum1 += __shfl_xor_sync(0xffffffffu, sum1, 2);
        l0 = l0 * corr0 + sum0;
        l1 = l1 * corr1 + sum1;
        #pragma unroll
        for (int nf = 0; nf < 8; nf++) {
            co[nf][0] *= corr0; co[nf][1] *= corr0;
            co[nf][2] *= corr1; co[nf][3] *= corr1;
        }
        #pragma unroll
        for (int kp = 0; kp < 4; kp++) {
            #pragma unroll
            for (int ng = 0; ng < 4; ng++) {
                uint32_t bh[4], bl[4];
                int bbase = (((lane & 7) + ((lane >> 3) & 1) * 8 + kp * 16) * AT_ST
                             + ng * 16 + ((lane >> 4) & 1) * 8) * 2;
                ldmx4t(bh, sVh + bbase);
                ldmx4t(bl, sVl + bbase);
                mma16816(co[2 * ng],     pfh[kp], &bh[0]);
                mma16816(co[2 * ng],     pfh[kp], &bl[0]);
                mma16816(co[2 * ng],     pfl[kp], &bh[0]);
                mma16816(co[2 * ng + 1], pfh[kp], &bh[2]);
                mma16816(co[2 * ng + 1], pfh[kp], &bl[2]);
                mma16816(co[2 * ng + 1], pfl[kp], &bh[2]);
            }
        }
    }
    float il0 = 1.f / l0, il1 = 1.f / l1;
    size_t base0 = (size_t)(b * TT + r_seq) * DD + h * HS;
    size_t base1 = base0 + (size_t)8 * DD;
    #pragma unroll
    for (int nf = 0; nf < 8; nf++) {
        int cc = nf * 8 + (lane & 3) * 2;
        float y0 = co[nf][0] * il0, y1 = co[nf][1] * il0;
        float y2 = co[nf][2] * il1, y3 = co[nf][3] * il1;
        __nv_bfloat16 h0, lo0, h1, lo1, h2, lo2, h3, lo3;
        bf16_split(y0, h0, lo0); bf16_split(y1, h1, lo1);
        bf16_split(y2, h2, lo2); bf16_split(y3, h3, lo3);
        *(__nv_bfloat162*)&g_yh[base0 + cc] = __halves2bfloat162(h0, h1);
        *(__nv_bfloat162*)&g_yl[base0 + cc] = __halves2bfloat162(lo0, lo1);
        *(__nv_bfloat162*)&g_yh[base1 + cc] = __halves2bfloat162(h2, h3);
        *(__nv_bfloat162*)&g_yl[base1 + cc] = __halves2bfloat162(lo2, lo3);
    }
}

static inline int sgrid(size_t n4) { return (int)((n4 + 255) / 256); }

extern "C" void kernel_launch(void* const* d_in, const int* in_sizes, int n_in,
                              void* d_out, int out_size) {
    const int*   idx   = (const int*)d_in[0];
    const float* embed = (const float*)d_in[1];
    const float* ln1   = (const float*)d_in[2];
    const float* qw    = (const float*)d_in[3];
    const float* kw    = (const float*)d_in[4];
    const float* vw    = (const float*)d_in[5];
    const float* ow    = (const float*)d_in[6];
    const float* ln2   = (const float*)d_in[7];
    const float* gw    = (const float*)d_in[8];
    const float* uw    = (const float*)d_in[9];
    const float* dw    = (const float*)d_in[10];
    const float* nw    = (const float*)d_in[11];
    float* out = (float*)d_out;

    float *px, *pqkv;
    cudaGetSymbolAddress((void**)&px,   g_x);
    cudaGetSymbolAddress((void**)&pqkv, g_qkv);
    __nv_bfloat16 *hh, *hl, *yh, *yl, *ah, *al;
    cudaGetSymbolAddress((void**)&hh, g_hh); cudaGetSymbolAddress((void**)&hl, g_hl);
    cudaGetSymbolAddress((void**)&yh, g_yh); cudaGetSymbolAddress((void**)&yl, g_yl);
    cudaGetSymbolAddress((void**)&ah, g_ah); cudaGetSymbolAddress((void**)&al, g_al);
    __half* fh; cudaGetSymbolAddress((void**)&fh, g_fh);
    __nv_bfloat16 *qkvwh, *qkvwl, *owh, *owl, *guwh, *guwl, *dwh, *dwl;
    __half *emh, *eml;
    cudaGetSymbolAddress((void**)&qkvwh, s_qkvw_h); cudaGetSymbolAddress((void**)&qkvwl, s_qkvw_l);
    cudaGetSymbolAddress((void**)&owh, s_ow_h);     cudaGetSymbolAddress((void**)&owl, s_ow_l);
    cudaGetSymbolAddress((void**)&guwh, s_guw_h);   cudaGetSymbolAddress((void**)&guwl, s_guw_l);
    cudaGetSymbolAddress((void**)&dwh, s_dw_h);     cudaGetSymbolAddress((void**)&dwl, s_dw_l);
    cudaGetSymbolAddress((void**)&emh, s_em_h);     cudaGetSymbolAddress((void**)&eml, s_em_l);

    // 2-stage dynamic smem sizes
    const int SM_G0 = 2 * (2 * (128 * 40) + 2 * (32 * 136)) * 2;   // 75776 B
    const int SM_G1 = 2 * (2 * (128 * 40) + 2 * (128 * 40)) * 2;   // 81920 B
    cudaFuncSetAttribute(bgemm<0, 0, 1, 0, 0, 0>, cudaFuncAttributeMaxDynamicSharedMemorySize, SM_G0);
    cudaFuncSetAttribute(bgemm<0, 1, 2, 0, 0, 0>, cudaFuncAttributeMaxDynamicSharedMemorySize, SM_G0);
    cudaFuncSetAttribute(bgemm<0, 0, 1, 0, 0, 1>, cudaFuncAttributeMaxDynamicSharedMemorySize, SM_G0);
    cudaFuncSetAttribute(bgemm<1, 0, 1, 1, 1, 0>, cudaFuncAttributeMaxDynamicSharedMemorySize, SM_G1);
    cudaFuncSetAttribute(attn_mma, cudaFuncAttributeMaxDynamicSharedMemorySize, ATN_SMEM);

    // prologue: pack/split weights
    pack_qkv4<<<NL * DD * 288 / 256, 256>>>(qw, kw, vw);
    pack_gu4 <<<NL * DD * 1024 / 256, 256>>>(gw, uw);
    split_kernel<<<sgrid((size_t)NL * DD * DD / 4), 256>>>(ow, owh, owl, NL * DD * DD / 4);
    split_kernel<<<sgrid((size_t)NL * II * DD / 4), 256>>>(dw, dwh, dwl, NL * II * DD / 4);
    split_kernel_h<<<sgrid((size_t)VV * DD / 4), 256>>>(embed, emh, eml, VV * DD / 4);

    dim3 gqkv(QKV / 128, BT / 128);           // (9,16)
    dim3 go(DD / 128, BT / 128, 2);           // (6,16,2) split-K
    dim3 ggu(GU / 128, BT / 128);             // (32,16) silu-fused
    dim3 ga(TT / 128, 2 * HH);                // (8,24)
    dim3 gl(BT / 128, (VV + 127) / 128);      // MSWAP: x=m(16), y=n(393)

    embed_kernel<<<BT, 192>>>(idx, embed);

    for (int l = 0; l < NL; l++) {
        size_t oQ  = (size_t)l * DD * QKV;
        size_t oO  = (size_t)l * DD * DD;
        size_t oG  = (size_t)l * DD * GU;
        size_t oD2 = (size_t)l * II * DD;
        rmsnorm_split<<<BT, 256>>>(px, ln1 + (size_t)l * DD, hh, hl);
        bgemm<0, 0, 1, 0, 0, 0><<<gqkv, 256, SM_G0>>>(hh, hl, qkvwh + oQ, qkvwl + oQ, pqkv, BT, QKV, DD);
        rope_split_kernel<<<BT, 576>>>();
        attn_mma<<<ga, 256, ATN_SMEM>>>();
        bgemm<0, 1, 2, 0, 0, 0><<<go, 256, SM_G0>>>(yh, yl, owh + oO, owl + oO, px, BT, DD, DD);
        rmsnorm_split<<<BT, 256>>>(px, ln2 + (size_t)l * DD, hh, hl);
        bgemm<0, 0, 1, 0, 0, 1><<<ggu, 256, SM_G0>>>(hh, hl, guwh + oG, guwl + oG, px, BT, GU, DD);
        bgemm<0, 1, 2, 0, 0, 0><<<go, 256, SM_G0>>>(ah, al, dwh + oD2, dwl + oD2, px, BT, DD, II);
    }
    rmsnorm_f16<<<BT, 256>>>(px, nw);
    bgemm<1, 0, 1, 1, 1, 0><<<gl, 256, SM_G1>>>(
        (const __nv_bfloat16*)fh, (const __nv_bfloat16*)fh,
        (const __nv_bfloat16*)emh, (const __nv_bfloat16*)eml, out, BT, VV, DD);
}

// round 12
// speedup vs baseline: 1.3973x; 1.2438x over previous
#include <cuda_runtime.h>
#include <cuda_bf16.h>
#include <cuda_fp16.h>
#include <math.h>
#include <stdint.h>

#define BT   2048
#define TT   1024
#define DD   768
#define HH   12
#define HS   64
#define NKV  3
#define NL   12
#define II   2048
#define VV   50257
#define KVD  192
#define QKV  1152
#define GU   4096
#define EPS_ 1e-6f
#define WSC  1024.0f
#define OSC  (1.0f / 1024.0f)

// fp32 scratch
__device__ float g_x[BT * DD];
__device__ float g_qkv[BT * QKV];
// fp16 single activations (GEMM A operands)
__device__ __half g_h16[BT * DD];
__device__ __half g_y16[BT * DD];
__device__ __half g_a16[BT * II];
// bf16 split qkv for attention
__device__ __nv_bfloat16 g_qkvh[BT * QKV], g_qkvl[BT * QKV];
// fp16 hi/lo weights, scaled x1024 ([K][N]; gu interleaved 2j=gate,2j+1=up)
__device__ __half s_qkvw_h[NL * DD * QKV], s_qkvw_l[NL * DD * QKV];
__device__ __half s_ow_h[NL * DD * DD],    s_ow_l[NL * DD * DD];
__device__ __half s_guw_h[NL * DD * GU],   s_guw_l[NL * DD * GU];
__device__ __half s_dw_h[NL * II * DD],    s_dw_l[NL * II * DD];
__device__ __half s_em_h[(size_t)VV * DD], s_em_l[(size_t)VV * DD];

__device__ __forceinline__ void bf16_split(float v, __nv_bfloat16& h, __nv_bfloat16& l) {
    h = __float2bfloat16(v);
    l = __float2bfloat16(v - __bfloat162float(h));
}
__device__ __forceinline__ void h16_split(float v, __half& h, __half& l) {
    v *= WSC;
    h = __float2half(v);
    l = __float2half(v - __half2float(h));
}
__device__ __forceinline__ uint32_t packbf(__nv_bfloat16 a, __nv_bfloat16 b) {
    __nv_bfloat162 t = __halves2bfloat162(a, b);
    return *(uint32_t*)&t;
}
__device__ __forceinline__ void ldmx4(uint32_t* r, uint32_t a) {
    asm volatile("ldmatrix.sync.aligned.m8n8.x4.shared.b16 {%0,%1,%2,%3}, [%4];"
                 : "=r"(r[0]), "=r"(r[1]), "=r"(r[2]), "=r"(r[3]) : "r"(a));
}
__device__ __forceinline__ void ldmx4t(uint32_t* r, uint32_t a) {
    asm volatile("ldmatrix.sync.aligned.m8n8.x4.trans.shared.b16 {%0,%1,%2,%3}, [%4];"
                 : "=r"(r[0]), "=r"(r[1]), "=r"(r[2]), "=r"(r[3]) : "r"(a));
}
__device__ __forceinline__ void mma16816(float* c, const uint32_t* a, const uint32_t* b) {
    asm volatile("mma.sync.aligned.m16n8k16.row.col.f32.bf16.bf16.f32 "
                 "{%0,%1,%2,%3}, {%4,%5,%6,%7}, {%8,%9}, {%0,%1,%2,%3};"
                 : "+f"(c[0]), "+f"(c[1]), "+f"(c[2]), "+f"(c[3])
                 : "r"(a[0]), "r"(a[1]), "r"(a[2]), "r"(a[3]), "r"(b[0]), "r"(b[1]));
}
__device__ __forceinline__ void mma16816h(float* c, const uint32_t* a, const uint32_t* b) {
    asm volatile("mma.sync.aligned.m16n8k16.row.col.f32.f16.f16.f32 "
                 "{%0,%1,%2,%3}, {%4,%5,%6,%7}, {%8,%9}, {%0,%1,%2,%3};"
                 : "+f"(c[0]), "+f"(c[1]), "+f"(c[2]), "+f"(c[3])
                 : "r"(a[0]), "r"(a[1]), "r"(a[2]), "r"(a[3]), "r"(b[0]), "r"(b[1]));
}
__device__ __forceinline__ void cpa16(uint32_t dst, const void* src) {
    asm volatile("cp.async.cg.shared.global [%0], [%1], 16;" :: "r"(dst), "l"(src));
}
__device__ __forceinline__ void cpcommit() { asm volatile("cp.async.commit_group;"); }
template<int N> __device__ __forceinline__ void cpwait() {
    asm volatile("cp.async.wait_group %0;" :: "n"(N));
}

// fp32 -> fp16 hi/lo (x1024) splitter
__global__ void split16(const float* __restrict__ s, __half* __restrict__ h,
                        __half* __restrict__ l, int n4) {
    int i = blockIdx.x * 256 + threadIdx.x;
    if (i >= n4) return;
    float4 v = ((const float4*)s)[i];
    __half h0, h1, h2, h3, l0, l1, l2, l3;
    h16_split(v.x, h0, l0); h16_split(v.y, h1, l1);
    h16_split(v.z, h2, l2); h16_split(v.w, h3, l3);
    __half2* hp = (__half2*)(h + (size_t)i * 4);
    __half2* lp = (__half2*)(l + (size_t)i * 4);
    hp[0] = __halves2half2(h0, h1); hp[1] = __halves2half2(h2, h3);
    lp[0] = __halves2half2(l0, l1); lp[1] = __halves2half2(l2, l3);
}

// pack qkv weights -> [D][1152] fp16 hi/lo x1024
__global__ void pack_qkv16(const float* __restrict__ qw, const float* __restrict__ kw,
                           const float* __restrict__ vw) {
    int i4 = blockIdx.x * 256 + threadIdx.x;
    int c4 = (i4 % 288) * 4;
    int rl = i4 / 288;
    int row = rl % DD, l = rl / DD;
    const float* src;
    if (c4 < DD)            src = qw + ((size_t)l * DD + row) * DD + c4;
    else if (c4 < DD + KVD) src = kw + ((size_t)l * DD + row) * KVD + (c4 - DD);
    else                    src = vw + ((size_t)l * DD + row) * KVD + (c4 - DD - KVD);
    float4 v = *(const float4*)src;
    __half h0, h1, h2, h3, l0, l1, l2, l3;
    h16_split(v.x, h0, l0); h16_split(v.y, h1, l1);
    h16_split(v.z, h2, l2); h16_split(v.w, h3, l3);
    __half2* hp = (__half2*)(s_qkvw_h + (size_t)i4 * 4);
    __half2* lp = (__half2*)(s_qkvw_l + (size_t)i4 * 4);
    hp[0] = __halves2half2(h0, h1); hp[1] = __halves2half2(h2, h3);
    lp[0] = __halves2half2(l0, l1); lp[1] = __halves2half2(l2, l3);
}

// pack gate/up interleaved -> [D][4096] fp16 hi/lo x1024
__global__ void pack_gu16(const float* __restrict__ gw, const float* __restrict__ uw) {
    int i4 = blockIdx.x * 256 + threadIdx.x;
    int c4 = (i4 & 1023) * 4;
    int rl = i4 >> 10;
    int row = rl % DD, l = rl / DD;
    int j = c4 >> 1;
    float2 gv = *(const float2*)(gw + ((size_t)l * DD + row) * II + j);
    float2 uv = *(const float2*)(uw + ((size_t)l * DD + row) * II + j);
    float4 v = make_float4(gv.x, uv.x, gv.y, uv.y);
    __half h0, h1, h2, h3, l0, l1, l2, l3;
    h16_split(v.x, h0, l0); h16_split(v.y, h1, l1);
    h16_split(v.z, h2, l2); h16_split(v.w, h3, l3);
    __half2* hp = (__half2*)(s_guw_h + (size_t)i4 * 4);
    __half2* lp = (__half2*)(s_guw_l + (size_t)i4 * 4);
    hp[0] = __halves2half2(h0, h1); hp[1] = __halves2half2(h2, h3);
    lp[0] = __halves2half2(l0, l1); lp[1] = __halves2half2(l2, l3);
}

__global__ void embed_kernel(const int* __restrict__ idx, const float* __restrict__ embed) {
    int row = blockIdx.x;
    const float4* src = (const float4*)(embed + (size_t)idx[row] * DD);
    ((float4*)(g_x + (size_t)row * DD))[threadIdx.x] = src[threadIdx.x];
}

// RMSNorm -> single fp16
__global__ __launch_bounds__(256) void rmsnorm16(const float* __restrict__ in,
                                                 const float* __restrict__ w,
                                                 __half* __restrict__ o) {
    int row = blockIdx.x;
    const float* x = in + (size_t)row * DD;
    float s = 0.f;
    for (int i = threadIdx.x; i < DD; i += 256) { float v = x[i]; s += v * v; }
    #pragma unroll
    for (int of = 16; of; of >>= 1) s += __shfl_xor_sync(0xffffffffu, s, of);
    __shared__ float red[8];
    if ((threadIdx.x & 31) == 0) red[threadIdx.x >> 5] = s;
    __syncthreads();
    if (threadIdx.x < 8) {
        s = red[threadIdx.x];
        #pragma unroll
        for (int of = 4; of; of >>= 1) s += __shfl_xor_sync(0xffu, s, of);
        if (threadIdx.x == 0) red[0] = s;
    }
    __syncthreads();
    float inv = rsqrtf(red[0] / (float)DD + EPS_);
    for (int i = threadIdx.x; i < DD; i += 256)
        o[(size_t)row * DD + i] = __float2half(w[i] * x[i] * inv);
}

// ---------------- fp16 2-term mma.sync GEMM, 3-stage cp.async pipeline ----------------
// C[M,N] = (A @ Bscaled) * 1/1024. A: fp16 single [M,K]. B: fp16 hi/lo.
// TRANSB==0: B[K,N]; TRANSB==1: B[N,K]. SPLITK: atomicAdd epilogue (partial*OSC).
// MSWAP: m from blockIdx.x. SILU: interleaved gate/up -> silu(g)*u -> g_a16 fp16.
template<int TRANSB, int SPLITK, int MSWAP, int SILU>
__global__ __launch_bounds__(256) void hgemm(const __half* __restrict__ A,
                                             const __half* __restrict__ Bh,
                                             const __half* __restrict__ Bl,
                                             float* __restrict__ C,
                                             int M, int N, int K) {
    constexpr int AST   = 40;
    constexpr int BROWS = TRANSB ? 128 : 32;
    constexpr int BST   = TRANSB ? 40  : 136;
    constexpr int ASZ   = 128 * AST;
    constexpr int BSZ   = BROWS * BST;
    constexpr int STG   = ASZ + 2 * BSZ;
    constexpr int NSTG  = 3;

    extern __shared__ __half smem[];
    int tid  = threadIdx.x;
    int lane = tid & 31, wid = tid >> 5;
    int wm = wid >> 2, wn = wid & 3;
    int row0 = (MSWAP ? blockIdx.x : blockIdx.y) * 128;
    int col0 = (MSWAP ? blockIdx.y : blockIdx.x) * 128;
    int kbeg = SPLITK > 1 ? blockIdx.z * (K / SPLITK) : 0;
    int klen = SPLITK > 1 ? (K / SPLITK) : K;

    float c[4][4][4] = {};
    uint32_t sbase = (uint32_t)__cvta_generic_to_shared(smem);
    int am = tid >> 2, aq = (tid & 3) * 8;

    auto load_stage = [&](int st, int k0) {
        uint32_t aoff = sbase + (uint32_t)st * STG * 2;
        #pragma unroll
        for (int i = 0; i < 2; i++) {
            int m = am + i * 64;
            cpa16(aoff + (m * AST + aq) * 2, A + (size_t)(row0 + m) * K + k0 + aq);
        }
        uint32_t boff = aoff + ASZ * 2;
        if (!TRANSB) {
            #pragma unroll
            for (int i = 0; i < 2; i++) {
                int k = (tid >> 4) + i * 16, q = (tid & 15) * 8;
                size_t g = (size_t)(k0 + k) * N + col0 + q;   // N % 128 == 0 here
                cpa16(boff + (k * BST + q) * 2, Bh + g);
                cpa16(boff + (BSZ + k * BST + q) * 2, Bl + g);
            }
        } else {
            #pragma unroll
            for (int i = 0; i < 2; i++) {
                int n = (tid >> 2) + i * 64, q = (tid & 3) * 8;
                if (col0 + n < N) {
                    size_t g = (size_t)(col0 + n) * K + k0 + q;
                    cpa16(boff + (n * BST + q) * 2, Bh + g);
                    cpa16(boff + (BSZ + n * BST + q) * 2, Bl + g);
                }
            }
        }
    };

    int nit = klen / 32;
    load_stage(0, kbeg);      cpcommit();
    load_stage(1, kbeg + 32); cpcommit();

    for (int it = 0; it < nit; it++) {
        int j = it + 2;
        if (j < nit)           { load_stage(j % NSTG, kbeg + j * 32); cpcommit(); cpwait<2>(); }
        else if (it + 1 < nit) { cpwait<1>(); }
        else                   { cpwait<0>(); }
        __syncthreads();

        int cur = it % NSTG;
        uint32_t sA   = sbase + (uint32_t)cur * STG * 2;
        uint32_t sB   = sA + ASZ * 2;
        uint32_t sBl_ = sB + BSZ * 2;

        #pragma unroll
        for (int kk = 0; kk < 32; kk += 16) {
            uint32_t fah[4][4], fbh[2][4], fbl[2][4];
            int abase = ((wm * 64 + (lane & 15)) * AST + (lane >> 4) * 8 + kk) * 2;
            #pragma unroll
            for (int mf = 0; mf < 4; mf++)
                ldmx4(fah[mf], sA + abase + mf * 16 * AST * 2);
            if (!TRANSB) {
                int bbase = (((lane & 7) + ((lane >> 3) & 1) * 8 + kk) * BST
                             + wn * 32 + ((lane >> 4) & 1) * 8) * 2;
                ldmx4t(fbh[0], sB + bbase);   ldmx4t(fbh[1], sB + bbase + 32);
                ldmx4t(fbl[0], sBl_ + bbase); ldmx4t(fbl[1], sBl_ + bbase + 32);
            } else {
                int bbase = ((wn * 32 + (lane & 7) + ((lane >> 4) & 1) * 8) * BST
                             + ((lane >> 3) & 1) * 8 + kk) * 2;
                ldmx4(fbh[0], sB + bbase);   ldmx4(fbh[1], sB + bbase + 16 * BST * 2);
                ldmx4(fbl[0], sBl_ + bbase); ldmx4(fbl[1], sBl_ + bbase + 16 * BST * 2);
            }
            #pragma unroll
            for (int mf = 0; mf < 4; mf++)
                #pragma unroll
                for (int nf = 0; nf < 4; nf++) {
                    mma16816h(c[mf][nf], fah[mf], &fbh[nf >> 1][(nf & 1) * 2]);
                    mma16816h(c[mf][nf], fah[mf], &fbl[nf >> 1][(nf & 1) * 2]);
                }
        }
        __syncthreads();
    }

    int g = lane >> 2, t = lane & 3;
    #pragma unroll
    for (int mf = 0; mf < 4; mf++) {
        #pragma unroll
        for (int nf = 0; nf < 4; nf++) {
            int r  = row0 + wm * 64 + mf * 16 + g;
            int cc = col0 + wn * 32 + nf * 8 + t * 2;
            if (SILU) {
                int j = cc >> 1;                     // cc even: (gate,up) pair
                float g0 = c[mf][nf][0] * OSC, u0 = c[mf][nf][1] * OSC;
                float g1 = c[mf][nf][2] * OSC, u1 = c[mf][nf][3] * OSC;
                g_a16[(size_t)r * II + j]       = __float2half(g0 / (1.f + __expf(-g0)) * u0);
                g_a16[(size_t)(r + 8) * II + j] = __float2half(g1 / (1.f + __expf(-g1)) * u1);
            } else if (SPLITK > 1) {
                float* p0 = C + (size_t)r * N + cc;
                float* p1 = C + (size_t)(r + 8) * N + cc;
                atomicAdd(p0,     c[mf][nf][0] * OSC); atomicAdd(p1,     c[mf][nf][2] * OSC);
                atomicAdd(p0 + 1, c[mf][nf][1] * OSC); atomicAdd(p1 + 1, c[mf][nf][3] * OSC);
            } else {
                float* p0 = C + (size_t)r * N + cc;
                float* p1 = C + (size_t)(r + 8) * N + cc;
                if (cc < N)     { p0[0] = c[mf][nf][0] * OSC; p1[0] = c[mf][nf][2] * OSC; }
                if (cc + 1 < N) { p0[1] = c[mf][nf][1] * OSC; p1[1] = c[mf][nf][3] * OSC; }
            }
        }
    }
}

// fused RoPE + bf16 hi/lo split of qkv (q pre-scaled 1/8) for attention
__global__ void rope_split_kernel() {
    int row = blockIdx.x;
    int t = row % TT;
    int i = threadIdx.x;                  // 576 = 18 heads * 32
    int head = i >> 5, d = i & 31;
    size_t base;
    float a0, a1;
    if (head < HH + NKV) {
        float sc = head < HH ? 0.125f : 1.0f;
        int off = head < HH ? head * HS : DD + (head - HH) * HS;
        base = (size_t)row * QKV + off;
        float freq = powf(10000.f, (float)d / 32.0f);
        float s, c;
        sincosf((float)t / freq, &s, &c);
        float xr = g_qkv[base + d], xi = g_qkv[base + d + 32];
        a0 = (xr * c - xi * s) * sc;
        a1 = (xi * c + xr * s) * sc;
    } else {
        base = (size_t)row * QKV + DD + KVD + (head - HH - NKV) * HS;
        a0 = g_qkv[base + d];
        a1 = g_qkv[base + d + 32];
    }
    __nv_bfloat16 h0, l0, h1, l1;
    bf16_split(a0, h0, l0); bf16_split(a1, h1, l1);
    g_qkvh[base + d] = h0;      g_qkvl[base + d] = l0;
    g_qkvh[base + d + 32] = h1; g_qkvl[base + d + 32] = l1;
}

// flash attention, bf16x3 mma.sync, 128-query tiles; epilogue -> fp16 y
#define AT_ST 72
#define ATN_SMEM ((2 * 128 * AT_ST + 4 * 64 * AT_ST) * 2)
__global__ __launch_bounds__(256) void attn_mma() {
    extern __shared__ __nv_bfloat16 sm[];
    __nv_bfloat16* Qh = sm;
    __nv_bfloat16* Ql = Qh + 128 * AT_ST;
    __nv_bfloat16* Kh = Ql + 128 * AT_ST;
    __nv_bfloat16* Kl = Kh + 64 * AT_ST;
    __nv_bfloat16* Vh = Kl + 64 * AT_ST;
    __nv_bfloat16* Vl = Vh + 64 * AT_ST;
    int tid = threadIdx.x, lane = tid & 31, w = tid >> 5;
    int q0 = blockIdx.x * 128;
    int b = blockIdx.y / HH, h = blockIdx.y % HH, kvh = h % NKV;
    uint32_t sQh = (uint32_t)__cvta_generic_to_shared(Qh);
    uint32_t sQl = (uint32_t)__cvta_generic_to_shared(Ql);
    uint32_t sKh = (uint32_t)__cvta_generic_to_shared(Kh);
    uint32_t sKl = (uint32_t)__cvta_generic_to_shared(Kl);
    uint32_t sVh = (uint32_t)__cvta_generic_to_shared(Vh);
    uint32_t sVl = (uint32_t)__cvta_generic_to_shared(Vl);

    for (int i = tid; i < 128 * 8; i += 256) {
        int row = i >> 3, q8 = (i & 7) * 8;
        size_t g = (size_t)(b * TT + q0 + row) * QKV + h * HS + q8;
        *(uint4*)&Qh[row * AT_ST + q8] = *(const uint4*)&g_qkvh[g];
        *(uint4*)&Ql[row * AT_ST + q8] = *(const uint4*)&g_qkvl[g];
    }
    __syncthreads();
    uint32_t qfh[4][4], qfl[4][4];
    {
        int abase = ((w * 16 + (lane & 15)) * AT_ST + (lane >> 4) * 8) * 2;
        #pragma unroll
        for (int kp = 0; kp < 4; kp++) {
            ldmx4(qfh[kp], sQh + abase + kp * 32);
            ldmx4(qfl[kp], sQl + abase + kp * 32);
        }
    }
    float m0 = -1e30f, m1 = -1e30f, l0 = 0.f, l1 = 0.f;
    float co[8][4] = {};
    int r_seq = q0 + w * 16 + (lane >> 2);
    int nt = q0 / 64 + 2;

    for (int it = 0; it < nt; it++) {
        int s0 = it * 64;
        __syncthreads();
        for (int i = tid; i < 64 * 8; i += 256) {
            int row = i >> 3, q8 = (i & 7) * 8;
            size_t gk = (size_t)(b * TT + s0 + row) * QKV + DD + kvh * HS + q8;
            size_t gv = gk + KVD;
            *(uint4*)&Kh[row * AT_ST + q8] = *(const uint4*)&g_qkvh[gk];
            *(uint4*)&Kl[row * AT_ST + q8] = *(const uint4*)&g_qkvl[gk];
            *(uint4*)&Vh[row * AT_ST + q8] = *(const uint4*)&g_qkvh[gv];
            *(uint4*)&Vl[row * AT_ST + q8] = *(const uint4*)&g_qkvl[gv];
        }
        __syncthreads();
        float cs[8][4] = {};
        #pragma unroll
        for (int kp = 0; kp < 4; kp++) {
            #pragma unroll
            for (int ng = 0; ng < 4; ng++) {
                uint32_t bh[4], bl[4];
                int bbase = ((ng * 16 + (lane & 7) + ((lane >> 4) & 1) * 8) * AT_ST
                             + ((lane >> 3) & 1) * 8 + kp * 16) * 2;
                ldmx4(bh, sKh + bbase);
                ldmx4(bl, sKl + bbase);
                mma16816(cs[2 * ng],     qfh[kp], &bh[0]);
                mma16816(cs[2 * ng],     qfh[kp], &bl[0]);
                mma16816(cs[2 * ng],     qfl[kp], &bh[0]);
                mma16816(cs[2 * ng + 1], qfh[kp], &bh[2]);
                mma16816(cs[2 * ng + 1], qfh[kp], &bl[2]);
                mma16816(cs[2 * ng + 1], qfl[kp], &bh[2]);
            }
        }
        if (s0 + 63 > q0 + w * 16) {
            #pragma unroll
            for (int nf = 0; nf < 8; nf++) {
                int key = s0 + nf * 8 + (lane & 3) * 2;
                if (key     > r_seq)     cs[nf][0] = -1e30f;
                if (key + 1 > r_seq)     cs[nf][1] = -1e30f;
                if (key     > r_seq + 8) cs[nf][2] = -1e30f;
                if (key + 1 > r_seq + 8) cs[nf][3] = -1e30f;
            }
        }
        float mx0 = cs[0][0], mx1 = cs[0][2];
        #pragma unroll
        for (int nf = 0; nf < 8; nf++) {
            mx0 = fmaxf(mx0, fmaxf(cs[nf][0], cs[nf][1]));
            mx1 = fmaxf(mx1, fmaxf(cs[nf][2], cs[nf][3]));
        }
        mx0 = fmaxf(mx0, __shfl_xor_sync(0xffffffffu, mx0, 1));
        mx0 = fmaxf(mx0, __shfl_xor_sync(0xffffffffu, mx0, 2));
        mx1 = fmaxf(mx1, __shfl_xor_sync(0xffffffffu, mx1, 1));
        mx1 = fmaxf(mx1, __shfl_xor_sync(0xffffffffu, mx1, 2));
        float nm0 = fmaxf(m0, mx0), nm1 = fmaxf(m1, mx1);
        float corr0 = __expf(m0 - nm0), corr1 = __expf(m1 - nm1);
        m0 = nm0; m1 = nm1;
        uint32_t pfh[4][4], pfl[4][4];
        float sum0 = 0.f, sum1 = 0.f;
        #pragma unroll
        for (int nf = 0; nf < 8; nf++) {
            float p0 = __expf(cs[nf][0] - nm0), p1 = __expf(cs[nf][1] - nm0);
            float p2 = __expf(cs[nf][2] - nm1), p3 = __expf(cs[nf][3] - nm1);
            sum0 += p0 + p1; sum1 += p2 + p3;
            __nv_bfloat16 h0, lo0, h1, lo1, h2, lo2, h3, lo3;
            bf16_split(p0, h0, lo0); bf16_split(p1, h1, lo1);
            bf16_split(p2, h2, lo2); bf16_split(p3, h3, lo3);
            int kp = nf >> 1, o = (nf & 1) * 2;
            pfh[kp][o]     = packbf(h0, h1);   pfh[kp][o + 1] = packbf(h2, h3);
            pfl[kp][o]     = packbf(lo0, lo1); pfl[kp][o + 1] = packbf(lo2, lo3);
        }
        sum0 += __shfl_xor_sync(0xffffffffu, sum0, 1);
        sum0 += __shfl_xor_sync(0xffffffffu, sum0, 2);
        sum1 += __shfl_xor_sync(0xffffffffu, sum1, 1);
        sum1 += __shfl_xor_sync(0xffffffffu, sum1, 2);
        l0 = l0 * corr0 + sum0;
        l1 = l1 * corr1 + sum1;
        #pragma unroll
        for (int nf = 0; nf < 8; nf++) {
            co[nf][0] *= corr0; co[nf][1] *= corr0;
            co[nf][2] *= corr1; co[nf][3] *= corr1;
        }
        #pragma unroll
        for (int kp = 0; kp < 4; kp++) {
            #pragma unroll
            for (int ng = 0; ng < 4; ng++) {
                uint32_t bh[4], bl[4];
                int bbase = (((lane & 7) + ((lane >> 3) & 1) * 8 + kp * 16) * AT_ST
                             + ng * 16 + ((lane >> 4) & 1) * 8) * 2;
                ldmx4t(bh, sVh + bbase);
                ldmx4t(bl, sVl + bbase);
                mma16816(co[2 * ng],     pfh[kp], &bh[0]);
                mma16816(co[2 * ng],     pfh[kp], &bl[0]);
                mma16816(co[2 * ng],     pfl[kp], &bh[0]);
                mma16816(co[2 * ng + 1], pfh[kp], &bh[2]);
                mma16816(co[2 * ng + 1], pfh[kp], &bl[2]);
                mma16816(co[2 * ng + 1], pfl[kp], &bh[2]);
            }
        }
    }
    float il0 = 1.f / l0, il1 = 1.f / l1;
    size_t base0 = (size_t)(b * TT + r_seq) * DD + h * HS;
    size_t base1 = base0 + (size_t)8 * DD;
    #pragma unroll
    for (int nf = 0; nf < 8; nf++) {
        int cc = nf * 8 + (lane & 3) * 2;
        *(__half2*)&g_y16[base0 + cc] = __halves2half2(
            __float2half(co[nf][0] * il0), __float2half(co[nf][1] * il0));
        *(__half2*)&g_y16[base1 + cc] = __halves2half2(
            __float2half(co[nf][2] * il1), __float2half(co[nf][3] * il1));
    }
}

static inline int sgrid(size_t n4) { return (int)((n4 + 255) / 256); }

extern "C" void kernel_launch(void* const* d_in, const int* in_sizes, int n_in,
                              void* d_out, int out_size) {
    const int*   idx   = (const int*)d_in[0];
    const float* embed = (const float*)d_in[1];
    const float* ln1   = (const float*)d_in[2];
    const float* qw    = (const float*)d_in[3];
    const float* kw    = (const float*)d_in[4];
    const float* vw    = (const float*)d_in[5];
    const float* ow    = (const float*)d_in[6];
    const float* ln2   = (const float*)d_in[7];
    const float* gw    = (const float*)d_in[8];
    const float* uw    = (const float*)d_in[9];
    const float* dw    = (const float*)d_in[10];
    const float* nw    = (const float*)d_in[11];
    float* out = (float*)d_out;

    float *px, *pqkv;
    cudaGetSymbolAddress((void**)&px,   g_x);
    cudaGetSymbolAddress((void**)&pqkv, g_qkv);
    __half *h16, *y16, *a16;
    cudaGetSymbolAddress((void**)&h16, g_h16);
    cudaGetSymbolAddress((void**)&y16, g_y16);
    cudaGetSymbolAddress((void**)&a16, g_a16);
    __half *qkvwh, *qkvwl, *owh, *owl, *guwh, *guwl, *dwh, *dwl, *emh, *eml;
    cudaGetSymbolAddress((void**)&qkvwh, s_qkvw_h); cudaGetSymbolAddress((void**)&qkvwl, s_qkvw_l);
    cudaGetSymbolAddress((void**)&owh, s_ow_h);     cudaGetSymbolAddress((void**)&owl, s_ow_l);
    cudaGetSymbolAddress((void**)&guwh, s_guw_h);   cudaGetSymbolAddress((void**)&guwl, s_guw_l);
    cudaGetSymbolAddress((void**)&dwh, s_dw_h);     cudaGetSymbolAddress((void**)&dwl, s_dw_l);
    cudaGetSymbolAddress((void**)&emh, s_em_h);     cudaGetSymbolAddress((void**)&eml, s_em_l);

    // 3-stage dynamic smem (fp16 single A plane)
    const int SM_G0 = 3 * (128 * 40 + 2 * 32 * 136) * 2;    // 82944 B
    const int SM_G1 = 3 * (128 * 40 + 2 * 128 * 40) * 2;    // 92160 B
    cudaFuncSetAttribute(hgemm<0, 1, 0, 0>, cudaFuncAttributeMaxDynamicSharedMemorySize, SM_G0);
    cudaFuncSetAttribute(hgemm<0, 2, 0, 0>, cudaFuncAttributeMaxDynamicSharedMemorySize, SM_G0);
    cudaFuncSetAttribute(hgemm<0, 1, 0, 1>, cudaFuncAttributeMaxDynamicSharedMemorySize, SM_G0);
    cudaFuncSetAttribute(hgemm<1, 1, 1, 0>, cudaFuncAttributeMaxDynamicSharedMemorySize, SM_G1);
    cudaFuncSetAttribute(attn_mma, cudaFuncAttributeMaxDynamicSharedMemorySize, ATN_SMEM);

    // prologue: pack/split weights (fp16 hi/lo x1024)
    pack_qkv16<<<NL * DD * 288 / 256, 256>>>(qw, kw, vw);
    pack_gu16 <<<NL * DD * 1024 / 256, 256>>>(gw, uw);
    split16<<<sgrid((size_t)NL * DD * DD / 4), 256>>>(ow, owh, owl, NL * DD * DD / 4);
    split16<<<sgrid((size_t)NL * II * DD / 4), 256>>>(dw, dwh, dwl, NL * II * DD / 4);
    split16<<<sgrid((size_t)VV * DD / 4), 256>>>(embed, emh, eml, VV * DD / 4);

    dim3 gqkv(QKV / 128, BT / 128);           // (9,16)
    dim3 go(DD / 128, BT / 128, 2);           // (6,16,2) split-K
    dim3 ggu(GU / 128, BT / 128);             // (32,16) silu-fused
    dim3 ga(TT / 128, 2 * HH);                // (8,24)
    dim3 gl(BT / 128, (VV + 127) / 128);      // MSWAP: x=m(16), y=n(393)

    embed_kernel<<<BT, 192>>>(idx, embed);

    for (int l = 0; l < NL; l++) {
        size_t oQ  = (size_t)l * DD * QKV;
        size_t oO  = (size_t)l * DD * DD;
        size_t oG  = (size_t)l * DD * GU;
        size_t oD2 = (size_t)l * II * DD;
        rmsnorm16<<<BT, 256>>>(px, ln1 + (size_t)l * DD, h16);
        hgemm<0, 1, 0, 0><<<gqkv, 256, SM_G0>>>(h16, qkvwh + oQ, qkvwl + oQ, pqkv, BT, QKV, DD);
        rope_split_kernel<<<BT, 576>>>();
        attn_mma<<<ga, 256, ATN_SMEM>>>();
        hgemm<0, 2, 0, 0><<<go, 256, SM_G0>>>(y16, owh + oO, owl + oO, px, BT, DD, DD);
        rmsnorm16<<<BT, 256>>>(px, ln2 + (size_t)l * DD, h16);
        hgemm<0, 1, 0, 1><<<ggu, 256, SM_G0>>>(h16, guwh + oG, guwl + oG, px, BT, GU, DD);
        hgemm<0, 2, 0, 0><<<go, 256, SM_G0>>>(a16, dwh + oD2, dwl + oD2, px, BT, DD, II);
    }
    rmsnorm16<<<BT, 256>>>(px, nw, h16);
    hgemm<1, 1, 1, 0><<<gl, 256, SM_G1>>>(h16, emh, eml, out, BT, VV, DD);
}

// round 13
// speedup vs baseline: 1.5497x; 1.1091x over previous
#include <cuda_runtime.h>
#include <cuda_fp16.h>
#include <math.h>
#include <stdint.h>

#define BT   2048
#define TT   1024
#define DD   768
#define HH   12
#define HS   64
#define NKV  3
#define NL   12
#define II   2048
#define VV   50257
#define KVD  192
#define QKV  1152
#define GU   4096
#define KV2  (2 * KVD)       // 384
#define EPS_ 1e-6f
#define WSC  1024.0f
#define OSC  (1.0f / 1024.0f)

// fp32 scratch
__device__ float g_x[BT * DD];
__device__ float g_qkv[BT * QKV];
// fp16 activations
__device__ __half g_h16[BT * DD];      // rmsnorm out
__device__ __half g_y16[BT * DD];      // attention out
__device__ __half g_a16[BT * II];      // silu*up out
__device__ __half g_q16[BT * DD];      // roped q (x 1/8)
__device__ __half g_kvh[BT * KV2], g_kvl[BT * KV2];   // k|v hi/lo
// rope tables
__device__ float g_rs[TT * 32], g_rc[TT * 32];
// fp16 hi/lo weights x1024 ([K][N]; gu interleaved 2j=gate,2j+1=up)
__device__ __half s_qkvw_h[NL * DD * QKV], s_qkvw_l[NL * DD * QKV];
__device__ __half s_ow_h[NL * DD * DD],    s_ow_l[NL * DD * DD];
__device__ __half s_guw_h[NL * DD * GU],   s_guw_l[NL * DD * GU];
__device__ __half s_dw_h[NL * II * DD],    s_dw_l[NL * II * DD];
// fp16 single embed [V][K]
__device__ __half s_em[(size_t)VV * DD];

__device__ __forceinline__ void h16_split(float v, __half& h, __half& l) {
    v *= WSC;
    h = __float2half(v);
    l = __float2half(v - __half2float(h));
}
__device__ __forceinline__ void h16_split0(float v, __half& h, __half& l) {
    h = __float2half(v);
    l = __float2half(v - __half2float(h));
}
__device__ __forceinline__ uint32_t packh(__half a, __half b) {
    __half2 t = __halves2half2(a, b);
    return *(uint32_t*)&t;
}
__device__ __forceinline__ void ldmx4(uint32_t* r, uint32_t a) {
    asm volatile("ldmatrix.sync.aligned.m8n8.x4.shared.b16 {%0,%1,%2,%3}, [%4];"
                 : "=r"(r[0]), "=r"(r[1]), "=r"(r[2]), "=r"(r[3]) : "r"(a));
}
__device__ __forceinline__ void ldmx4t(uint32_t* r, uint32_t a) {
    asm volatile("ldmatrix.sync.aligned.m8n8.x4.trans.shared.b16 {%0,%1,%2,%3}, [%4];"
                 : "=r"(r[0]), "=r"(r[1]), "=r"(r[2]), "=r"(r[3]) : "r"(a));
}
__device__ __forceinline__ void mma16816h(float* c, const uint32_t* a, const uint32_t* b) {
    asm volatile("mma.sync.aligned.m16n8k16.row.col.f32.f16.f16.f32 "
                 "{%0,%1,%2,%3}, {%4,%5,%6,%7}, {%8,%9}, {%0,%1,%2,%3};"
                 : "+f"(c[0]), "+f"(c[1]), "+f"(c[2]), "+f"(c[3])
                 : "r"(a[0]), "r"(a[1]), "r"(a[2]), "r"(a[3]), "r"(b[0]), "r"(b[1]));
}
__device__ __forceinline__ void cpa16(uint32_t dst, const void* src) {
    asm volatile("cp.async.cg.shared.global [%0], [%1], 16;" :: "r"(dst), "l"(src));
}
__device__ __forceinline__ void cpcommit() { asm volatile("cp.async.commit_group;"); }
template<int N> __device__ __forceinline__ void cpwait() {
    asm volatile("cp.async.wait_group %0;" :: "n"(N));
}

// fp32 -> fp16 hi/lo (x1024)
__global__ void split16(const float* __restrict__ s, __half* __restrict__ h,
                        __half* __restrict__ l, int n4) {
    int i = blockIdx.x * 256 + threadIdx.x;
    if (i >= n4) return;
    float4 v = ((const float4*)s)[i];
    __half h0, h1, h2, h3, l0, l1, l2, l3;
    h16_split(v.x, h0, l0); h16_split(v.y, h1, l1);
    h16_split(v.z, h2, l2); h16_split(v.w, h3, l3);
    __half2* hp = (__half2*)(h + (size_t)i * 4);
    __half2* lp = (__half2*)(l + (size_t)i * 4);
    hp[0] = __halves2half2(h0, h1); hp[1] = __halves2half2(h2, h3);
    lp[0] = __halves2half2(l0, l1); lp[1] = __halves2half2(l2, l3);
}

// fp32 -> single fp16 (embed)
__global__ void conv16(const float* __restrict__ s, __half* __restrict__ h, int n4) {
    int i = blockIdx.x * 256 + threadIdx.x;
    if (i >= n4) return;
    float4 v = ((const float4*)s)[i];
    __half2* hp = (__half2*)(h + (size_t)i * 4);
    hp[0] = __halves2half2(__float2half(v.x), __float2half(v.y));
    hp[1] = __halves2half2(__float2half(v.z), __float2half(v.w));
}

// pack qkv weights -> [D][1152] fp16 hi/lo x1024
__global__ void pack_qkv16(const float* __restrict__ qw, const float* __restrict__ kw,
                           const float* __restrict__ vw) {
    int i4 = blockIdx.x * 256 + threadIdx.x;
    int c4 = (i4 % 288) * 4;
    int rl = i4 / 288;
    int row = rl % DD, l = rl / DD;
    const float* src;
    if (c4 < DD)            src = qw + ((size_t)l * DD + row) * DD + c4;
    else if (c4 < DD + KVD) src = kw + ((size_t)l * DD + row) * KVD + (c4 - DD);
    else                    src = vw + ((size_t)l * DD + row) * KVD + (c4 - DD - KVD);
    float4 v = *(const float4*)src;
    __half h0, h1, h2, h3, l0, l1, l2, l3;
    h16_split(v.x, h0, l0); h16_split(v.y, h1, l1);
    h16_split(v.z, h2, l2); h16_split(v.w, h3, l3);
    __half2* hp = (__half2*)(s_qkvw_h + (size_t)i4 * 4);
    __half2* lp = (__half2*)(s_qkvw_l + (size_t)i4 * 4);
    hp[0] = __halves2half2(h0, h1); hp[1] = __halves2half2(h2, h3);
    lp[0] = __halves2half2(l0, l1); lp[1] = __halves2half2(l2, l3);
}

// pack gate/up interleaved -> [D][4096] fp16 hi/lo x1024
__global__ void pack_gu16(const float* __restrict__ gw, const float* __restrict__ uw) {
    int i4 = blockIdx.x * 256 + threadIdx.x;
    int c4 = (i4 & 1023) * 4;
    int rl = i4 >> 10;
    int row = rl % DD, l = rl / DD;
    int j = c4 >> 1;
    float2 gv = *(const float2*)(gw + ((size_t)l * DD + row) * II + j);
    float2 uv = *(const float2*)(uw + ((size_t)l * DD + row) * II + j);
    float4 v = make_float4(gv.x, uv.x, gv.y, uv.y);
    __half h0, h1, h2, h3, l0, l1, l2, l3;
    h16_split(v.x, h0, l0); h16_split(v.y, h1, l1);
    h16_split(v.z, h2, l2); h16_split(v.w, h3, l3);
    __half2* hp = (__half2*)(s_guw_h + (size_t)i4 * 4);
    __half2* lp = (__half2*)(s_guw_l + (size_t)i4 * 4);
    hp[0] = __halves2half2(h0, h1); hp[1] = __halves2half2(h2, h3);
    lp[0] = __halves2half2(l0, l1); lp[1] = __halves2half2(l2, l3);
}

// rope tables
__global__ void rope_table() {
    int t = blockIdx.x, d = threadIdx.x;
    float freq = powf(10000.f, (float)d / 32.0f);
    float s, c;
    sincosf((float)t / freq, &s, &c);
    g_rs[t * 32 + d] = s;
    g_rc[t * 32 + d] = c;
}

__global__ void embed_kernel(const int* __restrict__ idx, const float* __restrict__ embed) {
    int row = blockIdx.x;
    const float4* src = (const float4*)(embed + (size_t)idx[row] * DD);
    ((float4*)(g_x + (size_t)row * DD))[threadIdx.x] = src[threadIdx.x];
}

// RMSNorm -> single fp16
__global__ __launch_bounds__(256) void rmsnorm16(const float* __restrict__ in,
                                                 const float* __restrict__ w,
                                                 __half* __restrict__ o) {
    int row = blockIdx.x;
    const float* x = in + (size_t)row * DD;
    float s = 0.f;
    for (int i = threadIdx.x; i < DD; i += 256) { float v = x[i]; s += v * v; }
    #pragma unroll
    for (int of = 16; of; of >>= 1) s += __shfl_xor_sync(0xffffffffu, s, of);
    __shared__ float red[8];
    if ((threadIdx.x & 31) == 0) red[threadIdx.x >> 5] = s;
    __syncthreads();
    if (threadIdx.x < 8) {
        s = red[threadIdx.x];
        #pragma unroll
        for (int of = 4; of; of >>= 1) s += __shfl_xor_sync(0xffu, s, of);
        if (threadIdx.x == 0) red[0] = s;
    }
    __syncthreads();
    float inv = rsqrtf(red[0] / (float)DD + EPS_);
    for (int i = threadIdx.x; i < DD; i += 256)
        o[(size_t)row * DD + i] = __float2half(w[i] * x[i] * inv);
}

// ---------------- fp16 mma.sync GEMM, 3-stage cp.async pipeline ----------------
// TERMS=2: C = (A @ (Bh+Bl)) * 1/1024, B scaled x1024. TERMS=1: C = A @ Bh (unscaled).
// TRANSB==0: B[K,N]; TRANSB==1: B[N,K]. SPLITK: atomicAdd epilogue.
// MSWAP: m from blockIdx.x. SILU: interleaved gate/up -> silu(g)*u -> g_a16.
template<int TRANSB, int SPLITK, int MSWAP, int SILU, int TERMS>
__global__ __launch_bounds__(256) void hgemm(const __half* __restrict__ A,
                                             const __half* __restrict__ Bh,
                                             const __half* __restrict__ Bl,
                                             float* __restrict__ C,
                                             int M, int N, int K) {
    constexpr int AST   = 40;
    constexpr int BROWS = TRANSB ? 128 : 32;
    constexpr int BST   = TRANSB ? 40  : 136;
    constexpr int ASZ   = 128 * AST;
    constexpr int BSZ   = BROWS * BST;
    constexpr int STG   = ASZ + TERMS * BSZ;
    constexpr int NSTG  = 3;

    extern __shared__ __half smem[];
    int tid  = threadIdx.x;
    int lane = tid & 31, wid = tid >> 5;
    int wm = wid >> 2, wn = wid & 3;
    int row0 = (MSWAP ? blockIdx.x : blockIdx.y) * 128;
    int col0 = (MSWAP ? blockIdx.y : blockIdx.x) * 128;
    int kbeg = SPLITK > 1 ? blockIdx.z * (K / SPLITK) : 0;
    int klen = SPLITK > 1 ? (K / SPLITK) : K;

    float c[4][4][4] = {};
    uint32_t sbase = (uint32_t)__cvta_generic_to_shared(smem);
    int am = tid >> 2, aq = (tid & 3) * 8;

    auto load_stage = [&](int st, int k0) {
        uint32_t aoff = sbase + (uint32_t)st * STG * 2;
        #pragma unroll
        for (int i = 0; i < 2; i++) {
            int m = am + i * 64;
            cpa16(aoff + (m * AST + aq) * 2, A + (size_t)(row0 + m) * K + k0 + aq);
        }
        uint32_t boff = aoff + ASZ * 2;
        if (!TRANSB) {
            #pragma unroll
            for (int i = 0; i < 2; i++) {
                int k = (tid >> 4) + i * 16, q = (tid & 15) * 8;
                size_t g = (size_t)(k0 + k) * N + col0 + q;
                cpa16(boff + (k * BST + q) * 2, Bh + g);
                if (TERMS == 2) cpa16(boff + (BSZ + k * BST + q) * 2, Bl + g);
            }
        } else {
            #pragma unroll
            for (int i = 0; i < 2; i++) {
                int n = (tid >> 2) + i * 64, q = (tid & 3) * 8;
                if (col0 + n < N) {
                    size_t g = (size_t)(col0 + n) * K + k0 + q;
                    cpa16(boff + (n * BST + q) * 2, Bh + g);
                    if (TERMS == 2) cpa16(boff + (BSZ + n * BST + q) * 2, Bl + g);
                }
            }
        }
    };

    int nit = klen / 32;
    load_stage(0, kbeg);      cpcommit();
    load_stage(1, kbeg + 32); cpcommit();

    for (int it = 0; it < nit; it++) {
        int j = it + 2;
        if (j < nit)           { load_stage(j % NSTG, kbeg + j * 32); cpcommit(); cpwait<2>(); }
        else if (it + 1 < nit) { cpwait<1>(); }
        else                   { cpwait<0>(); }
        __syncthreads();

        int cur = it % NSTG;
        uint32_t sA   = sbase + (uint32_t)cur * STG * 2;
        uint32_t sB   = sA + ASZ * 2;
        uint32_t sBl_ = sB + BSZ * 2;

        #pragma unroll
        for (int kk = 0; kk < 32; kk += 16) {
            uint32_t fah[4][4], fbh[2][4], fbl[2][4];
            int abase = ((wm * 64 + (lane & 15)) * AST + (lane >> 4) * 8 + kk) * 2;
            #pragma unroll
            for (int mf = 0; mf < 4; mf++)
                ldmx4(fah[mf], sA + abase + mf * 16 * AST * 2);
            if (!TRANSB) {
                int bbase = (((lane & 7) + ((lane >> 3) & 1) * 8 + kk) * BST
                             + wn * 32 + ((lane >> 4) & 1) * 8) * 2;
                ldmx4t(fbh[0], sB + bbase);   ldmx4t(fbh[1], sB + bbase + 32);
                if (TERMS == 2) { ldmx4t(fbl[0], sBl_ + bbase); ldmx4t(fbl[1], sBl_ + bbase + 32); }
            } else {
                int bbase = ((wn * 32 + (lane & 7) + ((lane >> 4) & 1) * 8) * BST
                             + ((lane >> 3) & 1) * 8 + kk) * 2;
                ldmx4(fbh[0], sB + bbase);   ldmx4(fbh[1], sB + bbase + 16 * BST * 2);
                if (TERMS == 2) { ldmx4(fbl[0], sBl_ + bbase); ldmx4(fbl[1], sBl_ + bbase + 16 * BST * 2); }
            }
            #pragma unroll
            for (int mf = 0; mf < 4; mf++)
                #pragma unroll
                for (int nf = 0; nf < 4; nf++) {
                    mma16816h(c[mf][nf], fah[mf], &fbh[nf >> 1][(nf & 1) * 2]);
                    if (TERMS == 2) mma16816h(c[mf][nf], fah[mf], &fbl[nf >> 1][(nf & 1) * 2]);
                }
        }
        __syncthreads();
    }

    const float osc = (TERMS == 2) ? OSC : 1.0f;
    int g = lane >> 2, t = lane & 3;
    #pragma unroll
    for (int mf = 0; mf < 4; mf++) {
        #pragma unroll
        for (int nf = 0; nf < 4; nf++) {
            int r  = row0 + wm * 64 + mf * 16 + g;
            int cc = col0 + wn * 32 + nf * 8 + t * 2;
            if (SILU) {
                int j = cc >> 1;
                float g0 = c[mf][nf][0] * OSC, u0 = c[mf][nf][1] * OSC;
                float g1 = c[mf][nf][2] * OSC, u1 = c[mf][nf][3] * OSC;
                g_a16[(size_t)r * II + j]       = __float2half(g0 / (1.f + __expf(-g0)) * u0);
                g_a16[(size_t)(r + 8) * II + j] = __float2half(g1 / (1.f + __expf(-g1)) * u1);
            } else if (SPLITK > 1) {
                float* p0 = C + (size_t)r * N + cc;
                float* p1 = C + (size_t)(r + 8) * N + cc;
                atomicAdd(p0,     c[mf][nf][0] * osc); atomicAdd(p1,     c[mf][nf][2] * osc);
                atomicAdd(p0 + 1, c[mf][nf][1] * osc); atomicAdd(p1 + 1, c[mf][nf][3] * osc);
            } else {
                float* p0 = C + (size_t)r * N + cc;
                float* p1 = C + (size_t)(r + 8) * N + cc;
                if (cc < N)     { p0[0] = c[mf][nf][0] * osc; p1[0] = c[mf][nf][2] * osc; }
                if (cc + 1 < N) { p0[1] = c[mf][nf][1] * osc; p1[1] = c[mf][nf][3] * osc; }
            }
        }
    }
}

// fused RoPE (table-based) + fp16 outputs: q single (x1/8), k hi/lo, v hi/lo
__global__ void rope16() {
    int row = blockIdx.x;
    int t = row % TT;
    int i = threadIdx.x;                  // 576 = 18 heads * 32
    int head = i >> 5, d = i & 31;
    if (head < HH) {
        size_t base = (size_t)row * QKV + head * HS;
        float s = g_rs[t * 32 + d], c = g_rc[t * 32 + d];
        float xr = g_qkv[base + d], xi = g_qkv[base + d + 32];
        size_t ob = (size_t)row * DD + head * HS;
        g_q16[ob + d]      = __float2half((xr * c - xi * s) * 0.125f);
        g_q16[ob + d + 32] = __float2half((xi * c + xr * s) * 0.125f);
    } else if (head < HH + NKV) {
        int kh = head - HH;
        size_t base = (size_t)row * QKV + DD + kh * HS;
        float s = g_rs[t * 32 + d], c = g_rc[t * 32 + d];
        float xr = g_qkv[base + d], xi = g_qkv[base + d + 32];
        float a0 = xr * c - xi * s;
        float a1 = xi * c + xr * s;
        __half h0, l0, h1, l1;
        h16_split0(a0, h0, l0); h16_split0(a1, h1, l1);
        size_t ob = (size_t)row * KV2 + kh * HS;
        g_kvh[ob + d] = h0;      g_kvl[ob + d] = l0;
        g_kvh[ob + d + 32] = h1; g_kvl[ob + d + 32] = l1;
    } else {
        int vh = head - HH - NKV;
        size_t base = (size_t)row * QKV + DD + KVD + vh * HS;
        float a0 = g_qkv[base + d], a1 = g_qkv[base + d + 32];
        __half h0, l0, h1, l1;
        h16_split0(a0, h0, l0); h16_split0(a1, h1, l1);
        size_t ob = (size_t)row * KV2 + KVD + vh * HS;
        g_kvh[ob + d] = h0;      g_kvl[ob + d] = l0;
        g_kvh[ob + d + 32] = h1; g_kvl[ob + d + 32] = l1;
    }
}

// flash attention fp16: q single, k hi/lo, P single, V hi/lo; 128-query tiles
#define AT_ST 72
#define ATN_SMEM ((128 * AT_ST + 4 * 64 * AT_ST) * 2)
__global__ __launch_bounds__(256) void attn_mma() {
    extern __shared__ __half sm[];
    __half* Qs = sm;
    __half* Kh = Qs + 128 * AT_ST;
    __half* Kl = Kh + 64 * AT_ST;
    __half* Vh = Kl + 64 * AT_ST;
    __half* Vl = Vh + 64 * AT_ST;
    int tid = threadIdx.x, lane = tid & 31, w = tid >> 5;
    int q0 = blockIdx.x * 128;
    int b = blockIdx.y / HH, h = blockIdx.y % HH, kvh = h % NKV;
    uint32_t sQ  = (uint32_t)__cvta_generic_to_shared(Qs);
    uint32_t sKh = (uint32_t)__cvta_generic_to_shared(Kh);
    uint32_t sKl = (uint32_t)__cvta_generic_to_shared(Kl);
    uint32_t sVh = (uint32_t)__cvta_generic_to_shared(Vh);
    uint32_t sVl = (uint32_t)__cvta_generic_to_shared(Vl);

    for (int i = tid; i < 128 * 8; i += 256) {
        int row = i >> 3, q8 = (i & 7) * 8;
        *(uint4*)&Qs[row * AT_ST + q8] =
            *(const uint4*)&g_q16[(size_t)(b * TT + q0 + row) * DD + h * HS + q8];
    }
    __syncthreads();
    uint32_t qf[4][4];
    {
        int abase = ((w * 16 + (lane & 15)) * AT_ST + (lane >> 4) * 8) * 2;
        #pragma unroll
        for (int kp = 0; kp < 4; kp++)
            ldmx4(qf[kp], sQ + abase + kp * 32);
    }
    float m0 = -1e30f, m1 = -1e30f, l0 = 0.f, l1 = 0.f;
    float co[8][4] = {};
    int r_seq = q0 + w * 16 + (lane >> 2);
    int nt = q0 / 64 + 2;

    for (int it = 0; it < nt; it++) {
        int s0 = it * 64;
        __syncthreads();
        for (int i = tid; i < 64 * 8; i += 256) {
            int row = i >> 3, q8 = (i & 7) * 8;
            size_t gk = (size_t)(b * TT + s0 + row) * KV2 + kvh * HS + q8;
            size_t gv = gk + KVD;
            *(uint4*)&Kh[row * AT_ST + q8] = *(const uint4*)&g_kvh[gk];
            *(uint4*)&Kl[row * AT_ST + q8] = *(const uint4*)&g_kvl[gk];
            *(uint4*)&Vh[row * AT_ST + q8] = *(const uint4*)&g_kvh[gv];
            *(uint4*)&Vl[row * AT_ST + q8] = *(const uint4*)&g_kvl[gv];
        }
        __syncthreads();
        float cs[8][4] = {};
        #pragma unroll
        for (int kp = 0; kp < 4; kp++) {
            #pragma unroll
            for (int ng = 0; ng < 4; ng++) {
                uint32_t bh[4], bl[4];
                int bbase = ((ng * 16 + (lane & 7) + ((lane >> 4) & 1) * 8) * AT_ST
                             + ((lane >> 3) & 1) * 8 + kp * 16) * 2;
                ldmx4(bh, sKh + bbase);
                ldmx4(bl, sKl + bbase);
                mma16816h(cs[2 * ng],     qf[kp], &bh[0]);
                mma16816h(cs[2 * ng],     qf[kp], &bl[0]);
                mma16816h(cs[2 * ng + 1], qf[kp], &bh[2]);
                mma16816h(cs[2 * ng + 1], qf[kp], &bl[2]);
            }
        }
        if (s0 + 63 > q0 + w * 16) {
            #pragma unroll
            for (int nf = 0; nf < 8; nf++) {
                int key = s0 + nf * 8 + (lane & 3) * 2;
                if (key     > r_seq)     cs[nf][0] = -1e30f;
                if (key + 1 > r_seq)     cs[nf][1] = -1e30f;
                if (key     > r_seq + 8) cs[nf][2] = -1e30f;
                if (key + 1 > r_seq + 8) cs[nf][3] = -1e30f;
            }
        }
        float mx0 = cs[0][0], mx1 = cs[0][2];
        #pragma unroll
        for (int nf = 0; nf < 8; nf++) {
            mx0 = fmaxf(mx0, fmaxf(cs[nf][0], cs[nf][1]));
            mx1 = fmaxf(mx1, fmaxf(cs[nf][2], cs[nf][3]));
        }
        mx0 = fmaxf(mx0, __shfl_xor_sync(0xffffffffu, mx0, 1));
        mx0 = fmaxf(mx0, __shfl_xor_sync(0xffffffffu, mx0, 2));
        mx1 = fmaxf(mx1, __shfl_xor_sync(0xffffffffu, mx1, 1));
        mx1 = fmaxf(mx1, __shfl_xor_sync(0xffffffffu, mx1, 2));
        float nm0 = fmaxf(m0, mx0), nm1 = fmaxf(m1, mx1);
        float corr0 = __expf(m0 - nm0), corr1 = __expf(m1 - nm1);
        m0 = nm0; m1 = nm1;
        uint32_t pf[4][4];
        float sum0 = 0.f, sum1 = 0.f;
        #pragma unroll
        for (int nf = 0; nf < 8; nf++) {
            float p0 = __expf(cs[nf][0] - nm0), p1 = __expf(cs[nf][1] - nm0);
            float p2 = __expf(cs[nf][2] - nm1), p3 = __expf(cs[nf][3] - nm1);
            sum0 += p0 + p1; sum1 += p2 + p3;
            int kp = nf >> 1, o = (nf & 1) * 2;
            pf[kp][o]     = packh(__float2half(p0), __float2half(p1));
            pf[kp][o + 1] = packh(__float2half(p2), __float2half(p3));
        }
        sum0 += __shfl_xor_sync(0xffffffffu, sum0, 1);
        sum0 += __shfl_xor_sync(0xffffffffu, sum0, 2);
        sum1 += __shfl_xor_sync(0xffffffffu, sum1, 1);
        sum1 += __shfl_xor_sync(0xffffffffu, sum1, 2);
        l0 = l0 * corr0 + sum0;
        l1 = l1 * corr1 + sum1;
        #pragma unroll
        for (int nf = 0; nf < 8; nf++) {
            co[nf][0] *= corr0; co[nf][1] *= corr0;
            co[nf][2] *= corr1; co[nf][3] *= corr1;
        }
        #pragma unroll
        for (int kp = 0; kp < 4; kp++) {
            #pragma unroll
            for (int ng = 0; ng < 4; ng++) {
                uint32_t bh[4], bl[4];
                int bbase = (((lane & 7) + ((lane >> 3) & 1) * 8 + kp * 16) * AT_ST
                             + ng * 16 + ((lane >> 4) & 1) * 8) * 2;
                ldmx4t(bh, sVh + bbase);
                ldmx4t(bl, sVl + bbase);
                mma16816h(co[2 * ng],     pf[kp], &bh[0]);
                mma16816h(co[2 * ng],     pf[kp], &bl[0]);
                mma16816h(co[2 * ng + 1], pf[kp], &bh[2]);
                mma16816h(co[2 * ng + 1], pf[kp], &bl[2]);
            }
        }
    }
    float il0 = 1.f / l0, il1 = 1.f / l1;
    size_t base0 = (size_t)(b * TT + r_seq) * DD + h * HS;
    size_t base1 = base0 + (size_t)8 * DD;
    #pragma unroll
    for (int nf = 0; nf < 8; nf++) {
        int cc = nf * 8 + (lane & 3) * 2;
        *(__half2*)&g_y16[base0 + cc] = __halves2half2(
            __float2half(co[nf][0] * il0), __float2half(co[nf][1] * il0));
        *(__half2*)&g_y16[base1 + cc] = __halves2half2(
            __float2half(co[nf][2] * il1), __float2half(co[nf][3] * il1));
    }
}

static inline int sgrid(size_t n4) { return (int)((n4 + 255) / 256); }

extern "C" void kernel_launch(void* const* d_in, const int* in_sizes, int n_in,
                              void* d_out, int out_size) {
    const int*   idx   = (const int*)d_in[0];
    const float* embed = (const float*)d_in[1];
    const float* ln1   = (const float*)d_in[2];
    const float* qw    = (const float*)d_in[3];
    const float* kw    = (const float*)d_in[4];
    const float* vw    = (const float*)d_in[5];
    const float* ow    = (const float*)d_in[6];
    const float* ln2   = (const float*)d_in[7];
    const float* gw    = (const float*)d_in[8];
    const float* uw    = (const float*)d_in[9];
    const float* dw    = (const float*)d_in[10];
    const float* nw    = (const float*)d_in[11];
    float* out = (float*)d_out;

    float *px, *pqkv;
    cudaGetSymbolAddress((void**)&px,   g_x);
    cudaGetSymbolAddress((void**)&pqkv, g_qkv);
    __half *h16, *y16, *a16;
    cudaGetSymbolAddress((void**)&h16, g_h16);
    cudaGetSymbolAddress((void**)&y16, g_y16);
    cudaGetSymbolAddress((void**)&a16, g_a16);
    __half *qkvwh, *qkvwl, *owh, *owl, *guwh, *guwl, *dwh, *dwl, *em;
    cudaGetSymbolAddress((void**)&qkvwh, s_qkvw_h); cudaGetSymbolAddress((void**)&qkvwl, s_qkvw_l);
    cudaGetSymbolAddress((void**)&owh, s_ow_h);     cudaGetSymbolAddress((void**)&owl, s_ow_l);
    cudaGetSymbolAddress((void**)&guwh, s_guw_h);   cudaGetSymbolAddress((void**)&guwl, s_guw_l);
    cudaGetSymbolAddress((void**)&dwh, s_dw_h);     cudaGetSymbolAddress((void**)&dwl, s_dw_l);
    cudaGetSymbolAddress((void**)&em,  s_em);

    const int SM_G0 = 3 * (128 * 40 + 2 * 32 * 136) * 2;    // 82944 B (TERMS=2)
    const int SM_G1 = 3 * (128 * 40 + 128 * 40) * 2;        // 61440 B (TERMS=1, TRANSB=1)
    cudaFuncSetAttribute(hgemm<0, 1, 0, 0, 2>, cudaFuncAttributeMaxDynamicSharedMemorySize, SM_G0);
    cudaFuncSetAttribute(hgemm<0, 2, 0, 0, 2>, cudaFuncAttributeMaxDynamicSharedMemorySize, SM_G0);
    cudaFuncSetAttribute(hgemm<0, 1, 0, 1, 2>, cudaFuncAttributeMaxDynamicSharedMemorySize, SM_G0);
    cudaFuncSetAttribute(hgemm<1, 1, 1, 0, 1>, cudaFuncAttributeMaxDynamicSharedMemorySize, SM_G1);
    cudaFuncSetAttribute(attn_mma, cudaFuncAttributeMaxDynamicSharedMemorySize, ATN_SMEM);

    // prologue
    pack_qkv16<<<NL * DD * 288 / 256, 256>>>(qw, kw, vw);
    pack_gu16 <<<NL * DD * 1024 / 256, 256>>>(gw, uw);
    split16<<<sgrid((size_t)NL * DD * DD / 4), 256>>>(ow, owh, owl, NL * DD * DD / 4);
    split16<<<sgrid((size_t)NL * II * DD / 4), 256>>>(dw, dwh, dwl, NL * II * DD / 4);
    conv16<<<sgrid((size_t)VV * DD / 4), 256>>>(embed, em, VV * DD / 4);
    rope_table<<<TT, 32>>>();

    dim3 gqkv(QKV / 128, BT / 128);           // (9,16)
    dim3 go(DD / 128, BT / 128, 2);           // (6,16,2) split-K
    dim3 ggu(GU / 128, BT / 128);             // (32,16) silu-fused
    dim3 ga(TT / 128, 2 * HH);                // (8,24)
    dim3 gl(BT / 128, (VV + 127) / 128);      // MSWAP: x=m(16), y=n(393)

    embed_kernel<<<BT, 192>>>(idx, embed);

    for (int l = 0; l < NL; l++) {
        size_t oQ  = (size_t)l * DD * QKV;
        size_t oO  = (size_t)l * DD * DD;
        size_t oG  = (size_t)l * DD * GU;
        size_t oD2 = (size_t)l * II * DD;
        rmsnorm16<<<BT, 256>>>(px, ln1 + (size_t)l * DD, h16);
        hgemm<0, 1, 0, 0, 2><<<gqkv, 256, SM_G0>>>(h16, qkvwh + oQ, qkvwl + oQ, pqkv, BT, QKV, DD);
        rope16<<<BT, 576>>>();
        attn_mma<<<ga, 256, ATN_SMEM>>>();
        hgemm<0, 2, 0, 0, 2><<<go, 256, SM_G0>>>(y16, owh + oO, owl + oO, px, BT, DD, DD);
        rmsnorm16<<<BT, 256>>>(px, ln2 + (size_t)l * DD, h16);
        hgemm<0, 1, 0, 1, 2><<<ggu, 256, SM_G0>>>(h16, guwh + oG, guwl + oG, px, BT, GU, DD);
        hgemm<0, 2, 0, 0, 2><<<go, 256, SM_G0>>>(a16, dwh + oD2, dwl + oD2, px, BT, DD, II);
    }
    rmsnorm16<<<BT, 256>>>(px, nw, h16);
    hgemm<1, 1, 1, 0, 1><<<gl, 256, SM_G1>>>(h16, em, em, out, BT, VV, DD);
}

// round 16
// speedup vs baseline: 1.7596x; 1.1355x over previous
#include <cuda_runtime.h>
#include <cuda_fp16.h>
#include <math.h>
#include <stdint.h>

#define BT   2048
#define TT   1024
#define DD   768
#define HH   12
#define HS   64
#define NKV  3
#define NL   12
#define II   2048
#define VV   50257
#define KVD  192
#define QKV  1152
#define GU   4096
#define EPS_ 1e-6f
#define WSC  1024.0f
#define OSC  (1.0f / 1024.0f)

// fp32 residual
__device__ float g_x[BT * DD];
// fp16 activations
__device__ __half g_qkv16[BT * QKV];   // qkv GEMM out (un-roped; V read in place)
__device__ __half g_h16[BT * DD];      // rmsnorm out
__device__ __half g_y16[BT * DD];      // attention out
__device__ __half g_a16[BT * II];      // silu*up out
__device__ __half g_q16[BT * DD];      // roped q (x 1/8)
__device__ __half g_k16[BT * KVD];     // roped k
// rope tables
__device__ float g_rs[TT * 32], g_rc[TT * 32];
// fp16 hi/lo weights x1024 ([K][N]; gu interleaved 2j=gate,2j+1=up)
__device__ __half s_qkvw_h[NL * DD * QKV], s_qkvw_l[NL * DD * QKV];
__device__ __half s_ow_h[NL * DD * DD],    s_ow_l[NL * DD * DD];
__device__ __half s_guw_h[NL * DD * GU],   s_guw_l[NL * DD * GU];
__device__ __half s_dw_h[NL * II * DD],    s_dw_l[NL * II * DD];
// fp16 single embed [V][K]
__device__ __half s_em[(size_t)VV * DD];

__device__ __forceinline__ void h16_split(float v, __half& h, __half& l) {
    v *= WSC;
    h = __float2half(v);
    l = __float2half(v - __half2float(h));
}
__device__ __forceinline__ uint32_t packh(__half a, __half b) {
    __half2 t = __halves2half2(a, b);
    return *(uint32_t*)&t;
}
__device__ __forceinline__ void ldmx4(uint32_t* r, uint32_t a) {
    asm volatile("ldmatrix.sync.aligned.m8n8.x4.shared.b16 {%0,%1,%2,%3}, [%4];"
                 : "=r"(r[0]), "=r"(r[1]), "=r"(r[2]), "=r"(r[3]) : "r"(a));
}
__device__ __forceinline__ void ldmx4t(uint32_t* r, uint32_t a) {
    asm volatile("ldmatrix.sync.aligned.m8n8.x4.trans.shared.b16 {%0,%1,%2,%3}, [%4];"
                 : "=r"(r[0]), "=r"(r[1]), "=r"(r[2]), "=r"(r[3]) : "r"(a));
}
__device__ __forceinline__ void mma16816h(float* c, const uint32_t* a, const uint32_t* b) {
    asm volatile("mma.sync.aligned.m16n8k16.row.col.f32.f16.f16.f32 "
                 "{%0,%1,%2,%3}, {%4,%5,%6,%7}, {%8,%9}, {%0,%1,%2,%3};"
                 : "+f"(c[0]), "+f"(c[1]), "+f"(c[2]), "+f"(c[3])
                 : "r"(a[0]), "r"(a[1]), "r"(a[2]), "r"(a[3]), "r"(b[0]), "r"(b[1]));
}
__device__ __forceinline__ void cpa16(uint32_t dst, const void* src) {
    asm volatile("cp.async.cg.shared.global [%0], [%1], 16;" :: "r"(dst), "l"(src));
}
__device__ __forceinline__ void cpcommit() { asm volatile("cp.async.commit_group;"); }
template<int N> __device__ __forceinline__ void cpwait() {
    asm volatile("cp.async.wait_group %0;" :: "n"(N));
}

// fp32 -> fp16 hi/lo (x1024)
__global__ void split16(const float* __restrict__ s, __half* __restrict__ h,
                        __half* __restrict__ l, int n4) {
    int i = blockIdx.x * 256 + threadIdx.x;
    if (i >= n4) return;
    float4 v = ((const float4*)s)[i];
    __half h0, h1, h2, h3, l0, l1, l2, l3;
    h16_split(v.x, h0, l0); h16_split(v.y, h1, l1);
    h16_split(v.z, h2, l2); h16_split(v.w, h3, l3);
    __half2* hp = (__half2*)(h + (size_t)i * 4);
    __half2* lp = (__half2*)(l + (size_t)i * 4);
    hp[0] = __halves2half2(h0, h1); hp[1] = __halves2half2(h2, h3);
    lp[0] = __halves2half2(l0, l1); lp[1] = __halves2half2(l2, l3);
}

// fp32 -> single fp16 (embed)
__global__ void conv16(const float* __restrict__ s, __half* __restrict__ h, int n4) {
    int i = blockIdx.x * 256 + threadIdx.x;
    if (i >= n4) return;
    float4 v = ((const float4*)s)[i];
    __half2* hp = (__half2*)(h + (size_t)i * 4);
    hp[0] = __halves2half2(__float2half(v.x), __float2half(v.y));
    hp[1] = __halves2half2(__float2half(v.z), __float2half(v.w));
}

// pack qkv weights -> [D][1152] fp16 hi/lo x1024
__global__ void pack_qkv16(const float* __restrict__ qw, const float* __restrict__ kw,
                           const float* __restrict__ vw) {
    int i4 = blockIdx.x * 256 + threadIdx.x;
    int c4 = (i4 % 288) * 4;
    int rl = i4 / 288;
    int row = rl % DD, l = rl / DD;
    const float* src;
    if (c4 < DD)            src = qw + ((size_t)l * DD + row) * DD + c4;
    else if (c4 < DD + KVD) src = kw + ((size_t)l * DD + row) * KVD + (c4 - DD);
    else                    src = vw + ((size_t)l * DD + row) * KVD + (c4 - DD - KVD);
    float4 v = *(const float4*)src;
    __half h0, h1, h2, h3, l0, l1, l2, l3;
    h16_split(v.x, h0, l0); h16_split(v.y, h1, l1);
    h16_split(v.z, h2, l2); h16_split(v.w, h3, l3);
    __half2* hp = (__half2*)(s_qkvw_h + (size_t)i4 * 4);
    __half2* lp = (__half2*)(s_qkvw_l + (size_t)i4 * 4);
    hp[0] = __halves2half2(h0, h1); hp[1] = __halves2half2(h2, h3);
    lp[0] = __halves2half2(l0, l1); lp[1] = __halves2half2(l2, l3);
}

// pack gate/up interleaved -> [D][4096] fp16 hi/lo x1024
__global__ void pack_gu16(const float* __restrict__ gw, const float* __restrict__ uw) {
    int i4 = blockIdx.x * 256 + threadIdx.x;
    int c4 = (i4 & 1023) * 4;
    int rl = i4 >> 10;
    int row = rl % DD, l = rl / DD;
    int j = c4 >> 1;
    float2 gv = *(const float2*)(gw + ((size_t)l * DD + row) * II + j);
    float2 uv = *(const float2*)(uw + ((size_t)l * DD + row) * II + j);
    float4 v = make_float4(gv.x, uv.x, gv.y, uv.y);
    __half h0, h1, h2, h3, l0, l1, l2, l3;
    h16_split(v.x, h0, l0); h16_split(v.y, h1, l1);
    h16_split(v.z, h2, l2); h16_split(v.w, h3, l3);
    __half2* hp = (__half2*)(s_guw_h + (size_t)i4 * 4);
    __half2* lp = (__half2*)(s_guw_l + (size_t)i4 * 4);
    hp[0] = __halves2half2(h0, h1); hp[1] = __halves2half2(h2, h3);
    lp[0] = __halves2half2(l0, l1); lp[1] = __halves2half2(l2, l3);
}

// rope tables
__global__ void rope_table() {
    int t = blockIdx.x, d = threadIdx.x;
    float freq = powf(10000.f, (float)d / 32.0f);
    float s, c;
    sincosf((float)t / freq, &s, &c);
    g_rs[t * 32 + d] = s;
    g_rc[t * 32 + d] = c;
}

__global__ void embed_kernel(const int* __restrict__ idx, const float* __restrict__ embed) {
    int row = blockIdx.x;
    const float4* src = (const float4*)(embed + (size_t)idx[row] * DD);
    ((float4*)(g_x + (size_t)row * DD))[threadIdx.x] = src[threadIdx.x];
}

// RMSNorm -> single fp16
__global__ __launch_bounds__(256) void rmsnorm16(const float* __restrict__ in,
                                                 const float* __restrict__ w,
                                                 __half* __restrict__ o) {
    int row = blockIdx.x;
    const float* x = in + (size_t)row * DD;
    float s = 0.f;
    for (int i = threadIdx.x; i < DD; i += 256) { float v = x[i]; s += v * v; }
    #pragma unroll
    for (int of = 16; of; of >>= 1) s += __shfl_xor_sync(0xffffffffu, s, of);
    __shared__ float red[8];
    if ((threadIdx.x & 31) == 0) red[threadIdx.x >> 5] = s;
    __syncthreads();
    if (threadIdx.x < 8) {
        s = red[threadIdx.x];
        #pragma unroll
        for (int of = 4; of; of >>= 1) s += __shfl_xor_sync(0xffu, s, of);
        if (threadIdx.x == 0) red[0] = s;
    }
    __syncthreads();
    float inv = rsqrtf(red[0] / (float)DD + EPS_);
    for (int i = threadIdx.x; i < DD; i += 256)
        o[(size_t)row * DD + i] = __float2half(w[i] * x[i] * inv);
}

// ---------------- fp16 mma.sync GEMM, 3-stage cp.async pipeline ----------------
// TERMS=2: C = (A @ (Bh+Bl)) * 1/1024 (B x1024). TERMS=1: C = A @ Bh.
// TRANSB: B[N,K]. SPLITK: blockIdx.z K-range + fp32 atomicAdd. MSWAP: m fast.
// SILU: gate/up interleaved -> silu(g)*u -> g_a16. OUT16: C is __half*.
template<int TRANSB, int SPLITK, int MSWAP, int SILU, int TERMS, int OUT16>
__global__ __launch_bounds__(256) void hgemm(const __half* __restrict__ A,
                                             const __half* __restrict__ Bh,
                                             const __half* __restrict__ Bl,
                                             float* __restrict__ C,
                                             int M, int N, int K) {
    constexpr int AST   = 40;
    constexpr int BROWS = TRANSB ? 128 : 32;
    constexpr int BST   = TRANSB ? 40  : 136;
    constexpr int ASZ   = 128 * AST;
    constexpr int BSZ   = BROWS * BST;
    constexpr int STG   = ASZ + TERMS * BSZ;
    constexpr int NSTG  = 3;

    extern __shared__ __half smem[];
    int tid  = threadIdx.x;
    int lane = tid & 31, wid = tid >> 5;
    int wm = wid >> 2, wn = wid & 3;
    int row0 = (MSWAP ? blockIdx.x : blockIdx.y) * 128;
    int col0 = (MSWAP ? blockIdx.y : blockIdx.x) * 128;
    int kbeg = 0, klen = K;
    if (SPLITK > 1) {
        int kb = ((K / SPLITK) / 32) * 32;
        kbeg = blockIdx.z * kb;
        klen = (blockIdx.z == SPLITK - 1) ? (K - kb * (SPLITK - 1)) : kb;
    }

    float c[4][4][4] = {};
    uint32_t sbase = (uint32_t)__cvta_generic_to_shared(smem);
    int am = tid >> 2, aq = (tid & 3) * 8;

    auto load_stage = [&](int st, int k0) {
        uint32_t aoff = sbase + (uint32_t)st * STG * 2;
        #pragma unroll
        for (int i = 0; i < 2; i++) {
            int m = am + i * 64;
            cpa16(aoff + (m * AST + aq) * 2, A + (size_t)(row0 + m) * K + k0 + aq);
        }
        uint32_t boff = aoff + ASZ * 2;
        if (!TRANSB) {
            #pragma unroll
            for (int i = 0; i < 2; i++) {
                int k = (tid >> 4) + i * 16, q = (tid & 15) * 8;
                size_t g = (size_t)(k0 + k) * N + col0 + q;
                cpa16(boff + (k * BST + q) * 2, Bh + g);
                if (TERMS == 2) cpa16(boff + (BSZ + k * BST + q) * 2, Bl + g);
            }
        } else {
            #pragma unroll
            for (int i = 0; i < 2; i++) {
                int n = (tid >> 2) + i * 64, q = (tid & 3) * 8;
                if (col0 + n < N) {
                    size_t g = (size_t)(col0 + n) * K + k0 + q;
                    cpa16(boff + (n * BST + q) * 2, Bh + g);
                    if (TERMS == 2) cpa16(boff + (BSZ + n * BST + q) * 2, Bl + g);
                }
            }
        }
    };

    int nit = klen / 32;
    load_stage(0, kbeg);      cpcommit();
    load_stage(1, kbeg + 32); cpcommit();

    for (int it = 0; it < nit; it++) {
        int j = it + 2;
        if (j < nit)           { load_stage(j % NSTG, kbeg + j * 32); cpcommit(); cpwait<2>(); }
        else if (it + 1 < nit) { cpwait<1>(); }
        else                   { cpwait<0>(); }
        __syncthreads();

        int cur = it % NSTG;
        uint32_t sA   = sbase + (uint32_t)cur * STG * 2;
        uint32_t sB   = sA + ASZ * 2;
        uint32_t sBl_ = sB + BSZ * 2;

        #pragma unroll
        for (int kk = 0; kk < 32; kk += 16) {
            uint32_t fah[4][4], fbh[2][4], fbl[2][4];
            int abase = ((wm * 64 + (lane & 15)) * AST + (lane >> 4) * 8 + kk) * 2;
            #pragma unroll
            for (int mf = 0; mf < 4; mf++)
                ldmx4(fah[mf], sA + abase + mf * 16 * AST * 2);
            if (!TRANSB) {
                int bbase = (((lane & 7) + ((lane >> 3) & 1) * 8 + kk) * BST
                             + wn * 32 + ((lane >> 4) & 1) * 8) * 2;
                ldmx4t(fbh[0], sB + bbase);   ldmx4t(fbh[1], sB + bbase + 32);
                if (TERMS == 2) { ldmx4t(fbl[0], sBl_ + bbase); ldmx4t(fbl[1], sBl_ + bbase + 32); }
            } else {
                int bbase = ((wn * 32 + (lane & 7) + ((lane >> 4) & 1) * 8) * BST
                             + ((lane >> 3) & 1) * 8 + kk) * 2;
                ldmx4(fbh[0], sB + bbase);   ldmx4(fbh[1], sB + bbase + 16 * BST * 2);
                if (TERMS == 2) { ldmx4(fbl[0], sBl_ + bbase); ldmx4(fbl[1], sBl_ + bbase + 16 * BST * 2); }
            }
            #pragma unroll
            for (int mf = 0; mf < 4; mf++)
                #pragma unroll
                for (int nf = 0; nf < 4; nf++) {
                    mma16816h(c[mf][nf], fah[mf], &fbh[nf >> 1][(nf & 1) * 2]);
                    if (TERMS == 2) mma16816h(c[mf][nf], fah[mf], &fbl[nf >> 1][(nf & 1) * 2]);
                }
        }
        __syncthreads();
    }

    const float osc = (TERMS == 2) ? OSC : 1.0f;
    int g = lane >> 2, t = lane & 3;
    #pragma unroll
    for (int mf = 0; mf < 4; mf++) {
        #pragma unroll
        for (int nf = 0; nf < 4; nf++) {
            int r  = row0 + wm * 64 + mf * 16 + g;
            int cc = col0 + wn * 32 + nf * 8 + t * 2;
            if (SILU) {
                int j = cc >> 1;
                float g0 = c[mf][nf][0] * OSC, u0 = c[mf][nf][1] * OSC;
                float g1 = c[mf][nf][2] * OSC, u1 = c[mf][nf][3] * OSC;
                g_a16[(size_t)r * II + j]       = __float2half(g0 / (1.f + __expf(-g0)) * u0);
                g_a16[(size_t)(r + 8) * II + j] = __float2half(g1 / (1.f + __expf(-g1)) * u1);
            } else if (OUT16) {
                __half* H = (__half*)C;
                *(__half2*)&H[(size_t)r * N + cc] = __halves2half2(
                    __float2half(c[mf][nf][0] * osc), __float2half(c[mf][nf][1] * osc));
                *(__half2*)&H[(size_t)(r + 8) * N + cc] = __halves2half2(
                    __float2half(c[mf][nf][2] * osc), __float2half(c[mf][nf][3] * osc));
            } else if (SPLITK > 1) {
                float* p0 = C + (size_t)r * N + cc;
                float* p1 = C + (size_t)(r + 8) * N + cc;
                atomicAdd(p0,     c[mf][nf][0] * osc); atomicAdd(p1,     c[mf][nf][2] * osc);
                atomicAdd(p0 + 1, c[mf][nf][1] * osc); atomicAdd(p1 + 1, c[mf][nf][3] * osc);
            } else {
                float* p0 = C + (size_t)r * N + cc;
                float* p1 = C + (size_t)(r + 8) * N + cc;
                if (cc < N)     { p0[0] = c[mf][nf][0] * osc; p1[0] = c[mf][nf][2] * osc; }
                if (cc + 1 < N) { p0[1] = c[mf][nf][1] * osc; p1[1] = c[mf][nf][3] * osc; }
            }
        }
    }
}

// fused RoPE (table-based): q -> g_q16 (x1/8), k -> g_k16. V stays in g_qkv16.
__global__ void rope16() {
    int row = blockIdx.x;
    int t = row % TT;
    int i = threadIdx.x;                  // 480 = 15 heads * 32
    int head = i >> 5, d = i & 31;
    float s = g_rs[t * 32 + d], c = g_rc[t * 32 + d];
    if (head < HH) {
        size_t base = (size_t)row * QKV + head * HS;
        float xr = __half2float(g_qkv16[base + d]);
        float xi = __half2float(g_qkv16[base + d + 32]);
        size_t ob = (size_t)row * DD + head * HS;
        g_q16[ob + d]      = __float2half((xr * c - xi * s) * 0.125f);
        g_q16[ob + d + 32] = __float2half((xi * c + xr * s) * 0.125f);
    } else {
        int kh = head - HH;
        size_t base = (size_t)row * QKV + DD + kh * HS;
        float xr = __half2float(g_qkv16[base + d]);
        float xi = __half2float(g_qkv16[base + d + 32]);
        size_t ob = (size_t)row * KVD + kh * HS;
        g_k16[ob + d]      = __float2half(xr * c - xi * s);
        g_k16[ob + d + 32] = __float2half(xi * c + xr * s);
    }
}

// flash attention, all-fp16 single-plane, 128-query tiles, reversed CTA order
#define AT_ST 72
#define ATN_SMEM ((128 * AT_ST + 2 * 64 * AT_ST) * 2)   // 36864 B
__global__ __launch_bounds__(256) void attn_mma() {
    extern __shared__ __half sm[];
    __half* Qs = sm;
    __half* Ks = Qs + 128 * AT_ST;
    __half* Vs = Ks + 64 * AT_ST;
    int tid = threadIdx.x, lane = tid & 31, w = tid >> 5;
    int q0 = (gridDim.x - 1 - blockIdx.x) * 128;     // heavy CTAs first
    int b = blockIdx.y / HH, h = blockIdx.y % HH, kvh = h % NKV;
    uint32_t sQ = (uint32_t)__cvta_generic_to_shared(Qs);
    uint32_t sK = (uint32_t)__cvta_generic_to_shared(Ks);
    uint32_t sV = (uint32_t)__cvta_generic_to_shared(Vs);

    for (int i = tid; i < 128 * 8; i += 256) {
        int row = i >> 3, q8 = (i & 7) * 8;
        *(uint4*)&Qs[row * AT_ST + q8] =
            *(const uint4*)&g_q16[(size_t)(b * TT + q0 + row) * DD + h * HS + q8];
    }
    __syncthreads();
    uint32_t qf[4][4];
    {
        int abase = ((w * 16 + (lane & 15)) * AT_ST + (lane >> 4) * 8) * 2;
        #pragma unroll
        for (int kp = 0; kp < 4; kp++)
            ldmx4(qf[kp], sQ + abase + kp * 32);
    }
    float m0 = -1e30f, m1 = -1e30f, l0 = 0.f, l1 = 0.f;
    float co[8][4] = {};
    int r_seq = q0 + w * 16 + (lane >> 2);
    int nt = q0 / 64 + 2;

    for (int it = 0; it < nt; it++) {
        int s0 = it * 64;
        __syncthreads();
        for (int i = tid; i < 64 * 8; i += 256) {
            int row = i >> 3, q8 = (i & 7) * 8;
            *(uint4*)&Ks[row * AT_ST + q8] =
                *(const uint4*)&g_k16[(size_t)(b * TT + s0 + row) * KVD + kvh * HS + q8];
            *(uint4*)&Vs[row * AT_ST + q8] =
                *(const uint4*)&g_qkv16[(size_t)(b * TT + s0 + row) * QKV + DD + KVD + kvh * HS + q8];
        }
        __syncthreads();
        float cs[8][4] = {};
        #pragma unroll
        for (int kp = 0; kp < 4; kp++) {
            #pragma unroll
            for (int ng = 0; ng < 4; ng++) {
                uint32_t bk[4];
                int bbase = ((ng * 16 + (lane & 7) + ((lane >> 4) & 1) * 8) * AT_ST
                             + ((lane >> 3) & 1) * 8 + kp * 16) * 2;
                ldmx4(bk, sK + bbase);
                mma16816h(cs[2 * ng],     qf[kp], &bk[0]);
                mma16816h(cs[2 * ng + 1], qf[kp], &bk[2]);
            }
        }
        if (s0 + 63 > q0 + w * 16) {
            #pragma unroll
            for (int nf = 0; nf < 8; nf++) {
                int key = s0 + nf * 8 + (lane & 3) * 2;
                if (key     > r_seq)     cs[nf][0] = -1e30f;
                if (key + 1 > r_seq)     cs[nf][1] = -1e30f;
                if (key     > r_seq + 8) cs[nf][2] = -1e30f;
                if (key + 1 > r_seq + 8) cs[nf][3] = -1e30f;
            }
        }
        float mx0 = cs[0][0], mx1 = cs[0][2];
        #pragma unroll
        for (int nf = 0; nf < 8; nf++) {
            mx0 = fmaxf(mx0, fmaxf(cs[nf][0], cs[nf][1]));
            mx1 = fmaxf(mx1, fmaxf(cs[nf][2], cs[nf][3]));
        }
        mx0 = fmaxf(mx0, __shfl_xor_sync(0xffffffffu, mx0, 1));
        mx0 = fmaxf(mx0, __shfl_xor_sync(0xffffffffu, mx0, 2));
        mx1 = fmaxf(mx1, __shfl_xor_sync(0xffffffffu, mx1, 1));
        mx1 = fmaxf(mx1, __shfl_xor_sync(0xffffffffu, mx1, 2));
        float nm0 = fmaxf(m0, mx0), nm1 = fmaxf(m1, mx1);
        float corr0 = __expf(m0 - nm0), corr1 = __expf(m1 - nm1);
        m0 = nm0; m1 = nm1;
        uint32_t pf[4][4];
        float sum0 = 0.f, sum1 = 0.f;
        #pragma unroll
        for (int nf = 0; nf < 8; nf++) {
            float p0 = __expf(cs[nf][0] - nm0), p1 = __expf(cs[nf][1] - nm0);
            float p2 = __expf(cs[nf][2] - nm1), p3 = __expf(cs[nf][3] - nm1);
            sum0 += p0 + p1; sum1 += p2 + p3;
            int kp = nf >> 1, o = (nf & 1) * 2;
            pf[kp][o]     = packh(__float2half(p0), __float2half(p1));
            pf[kp][o + 1] = packh(__float2half(p2), __float2half(p3));
        }
        sum0 += __shfl_xor_sync(0xffffffffu, sum0, 1);
        sum0 += __shfl_xor_sync(0xffffffffu, sum0, 2);
        sum1 += __shfl_xor_sync(0xffffffffu, sum1, 1);
        sum1 += __shfl_xor_sync(0xffffffffu, sum1, 2);
        l0 = l0 * corr0 + sum0;
        l1 = l1 * corr1 + sum1;
        #pragma unroll
        for (int nf = 0; nf < 8; nf++) {
            co[nf][0] *= corr0; co[nf][1] *= corr0;
            co[nf][2] *= corr1; co[nf][3] *= corr1;
        }
        #pragma unroll
        for (int kp = 0; kp < 4; kp++) {
            #pragma unroll
            for (int ng = 0; ng < 4; ng++) {
                uint32_t bv[4];
                int bbase = (((lane & 7) + ((lane >> 3) & 1) * 8 + kp * 16) * AT_ST
                             + ng * 16 + ((lane >> 4) & 1) * 8) * 2;
                ldmx4t(bv, sV + bbase);
                mma16816h(co[2 * ng],     pf[kp], &bv[0]);
                mma16816h(co[2 * ng + 1], pf[kp], &bv[2]);
            }
        }
    }
    float il0 = 1.f / l0, il1 = 1.f / l1;
    size_t base0 = (size_t)(b * TT + r_seq) * DD + h * HS;
    size_t base1 = base0 + (size_t)8 * DD;
    #pragma unroll
    for (int nf = 0; nf < 8; nf++) {
        int cc = nf * 8 + (lane & 3) * 2;
        *(__half2*)&g_y16[base0 + cc] = __halves2half2(
            __float2half(co[nf][0] * il0), __float2half(co[nf][1] * il0));
        *(__half2*)&g_y16[base1 + cc] = __halves2half2(
            __float2half(co[nf][2] * il1), __float2half(co[nf][3] * il1));
    }
}

static inline int sgrid(size_t n4) { return (int)((n4 + 255) / 256); }

extern "C" void kernel_launch(void* const* d_in, const int* in_sizes, int n_in,
                              void* d_out, int out_size) {
    const int*   idx   = (const int*)d_in[0];
    const float* embed = (const float*)d_in[1];
    const float* ln1   = (const float*)d_in[2];
    const float* qw    = (const float*)d_in[3];
    const float* kw    = (const float*)d_in[4];
    const float* vw    = (const float*)d_in[5];
    const float* ow    = (const float*)d_in[6];
    const float* ln2   = (const float*)d_in[7];
    const float* gw    = (const float*)d_in[8];
    const float* uw    = (const float*)d_in[9];
    const float* dw    = (const float*)d_in[10];
    const float* nw    = (const float*)d_in[11];
    float* out = (float*)d_out;

    float* px;
    cudaGetSymbolAddress((void**)&px, g_x);
    __half *h16, *y16, *a16, *qkv16;
    cudaGetSymbolAddress((void**)&h16, g_h16);
    cudaGetSymbolAddress((void**)&y16, g_y16);
    cudaGetSymbolAddress((void**)&a16, g_a16);
    cudaGetSymbolAddress((void**)&qkv16, g_qkv16);
    __half *qkvwh, *qkvwl, *owh, *owl, *guwh, *guwl, *dwh, *dwl, *em;
    cudaGetSymbolAddress((void**)&qkvwh, s_qkvw_h); cudaGetSymbolAddress((void**)&qkvwl, s_qkvw_l);
    cudaGetSymbolAddress((void**)&owh, s_ow_h);     cudaGetSymbolAddress((void**)&owl, s_ow_l);
    cudaGetSymbolAddress((void**)&guwh, s_guw_h);   cudaGetSymbolAddress((void**)&guwl, s_guw_l);
    cudaGetSymbolAddress((void**)&dwh, s_dw_h);     cudaGetSymbolAddress((void**)&dwl, s_dw_l);
    cudaGetSymbolAddress((void**)&em,  s_em);

    const int SM_G0 = 3 * (128 * 40 + 2 * 32 * 136) * 2;    // 82944 B (TERMS=2)
    const int SM_G1 = 3 * (128 * 40 + 128 * 40) * 2;        // 61440 B (TERMS=1, TRANSB=1)
    cudaFuncSetAttribute(hgemm<0, 1, 0, 0, 2, 1>, cudaFuncAttributeMaxDynamicSharedMemorySize, SM_G0);
    cudaFuncSetAttribute(hgemm<0, 3, 0, 0, 2, 0>, cudaFuncAttributeMaxDynamicSharedMemorySize, SM_G0);
    cudaFuncSetAttribute(hgemm<0, 1, 0, 1, 2, 0>, cudaFuncAttributeMaxDynamicSharedMemorySize, SM_G0);
    cudaFuncSetAttribute(hgemm<1, 1, 1, 0, 1, 0>, cudaFuncAttributeMaxDynamicSharedMemorySize, SM_G1);
    cudaFuncSetAttribute(attn_mma, cudaFuncAttributeMaxDynamicSharedMemorySize, ATN_SMEM);

    // prologue
    pack_qkv16<<<NL * DD * 288 / 256, 256>>>(qw, kw, vw);
    pack_gu16 <<<NL * DD * 1024 / 256, 256>>>(gw, uw);
    split16<<<sgrid((size_t)NL * DD * DD / 4), 256>>>(ow, owh, owl, NL * DD * DD / 4);
    split16<<<sgrid((size_t)NL * II * DD / 4), 256>>>(dw, dwh, dwl, NL * II * DD / 4);
    conv16<<<sgrid((size_t)VV * DD / 4), 256>>>(embed, em, VV * DD / 4);
    rope_table<<<TT, 32>>>();

    dim3 gqkv(QKV / 128, BT / 128);           // (9,16)
    dim3 go(DD / 128, BT / 128, 3);           // (6,16,3) split-K=3
    dim3 ggu(GU / 128, BT / 128);             // (32,16) silu-fused
    dim3 ga(TT / 128, 2 * HH);                // (8,24)
    dim3 gl(BT / 128, (VV + 127) / 128);      // MSWAP: x=m(16), y=n(393)

    embed_kernel<<<BT, 192>>>(idx, embed);

    for (int l = 0; l < NL; l++) {
        size_t oQ  = (size_t)l * DD * QKV;
        size_t oO  = (size_t)l * DD * DD;
        size_t oG  = (size_t)l * DD * GU;
        size_t oD2 = (size_t)l * II * DD;
        rmsnorm16<<<BT, 256>>>(px, ln1 + (size_t)l * DD, h16);
        hgemm<0, 1, 0, 0, 2, 1><<<gqkv, 256, SM_G0>>>(h16, qkvwh + oQ, qkvwl + oQ,
                                                      (float*)qkv16, BT, QKV, DD);
        rope16<<<BT, 480>>>();
        attn_mma<<<ga, 256, ATN_SMEM>>>();
        hgemm<0, 3, 0, 0, 2, 0><<<go, 256, SM_G0>>>(y16, owh + oO, owl + oO, px, BT, DD, DD);
        rmsnorm16<<<BT, 256>>>(px, ln2 + (size_t)l * DD, h16);
        hgemm<0, 1, 0, 1, 2, 0><<<ggu, 256, SM_G0>>>(h16, guwh + oG, guwl + oG, px, BT, GU, DD);
        hgemm<0, 3, 0, 0, 2, 0><<<go, 256, SM_G0>>>(a16, dwh + oD2, dwl + oD2, px, BT, DD, II);
    }
    rmsnorm16<<<BT, 256>>>(px, nw, h16);
    hgemm<1, 1, 1, 0, 1, 0><<<gl, 256, SM_G1>>>(h16, em, em, out, BT, VV, DD);
}